// round 1
// baseline (speedup 1.0000x reference)
#include <cuda_runtime.h>
#include <cstdint>

// Problem constants
#define T_TOK   4096
#define DM      1024
#define HID     2048
#define NEXP    8
#define PADMAX  9216        // 2*T + 8*128 worst-case expert padding

// GEMM tiling
#define BM 128
#define BN 128
#define KC 16
#define ASTR (KC + 4)       // 20  (conflict-free A-frag loads)
#define BSTR (BN + 8)       // 136 (conflict-free B-frag loads)

// ---------------- scratch (device globals: allocation-free) ----------------
__device__ int   g_counts[NEXP];
__device__ int   g_seg[NEXP + 1];
__device__ int   g_cursor[NEXP];
__device__ int   g_topk_idx[T_TOK * 2];
__device__ float g_topk_gate[T_TOK * 2];
__device__ int   g_perm_token[PADMAX];
__device__ int   g_inv[T_TOK * 2];
__device__ float g_act[(size_t)PADMAX * HID];     // routed SwiGLU activations
__device__ float g_y[(size_t)PADMAX * DM];        // routed expert outputs
__device__ float g_shact[(size_t)T_TOK * HID];    // shared-expert activations

// ---------------- helpers ----------------
__device__ __forceinline__ float f2tf32(float x) {
    unsigned u;
    asm("cvt.rna.tf32.f32 %0, %1;" : "=r"(u) : "f"(x));
    return __uint_as_float(u);
}

__device__ __forceinline__ void mma_tf32(float* d, const unsigned* a, const unsigned* b) {
    asm volatile(
        "mma.sync.aligned.m16n8k8.row.col.f32.tf32.tf32.f32 "
        "{%0,%1,%2,%3}, {%4,%5,%6,%7}, {%8,%9}, {%0,%1,%2,%3};\n"
        : "+f"(d[0]), "+f"(d[1]), "+f"(d[2]), "+f"(d[3])
        : "r"(a[0]), "r"(a[1]), "r"(a[2]), "r"(a[3]), "r"(b[0]), "r"(b[1]));
}

__device__ __forceinline__ float silu_f(float h) {
    return __fdividef(h, 1.0f + __expf(-h));
}

// ---------------- stage 0: reset ----------------
__global__ void reset_kernel() {
    int i = blockIdx.x * blockDim.x + threadIdx.x;
    if (i < NEXP) g_counts[i] = 0;
    for (int p = i; p < PADMAX; p += gridDim.x * blockDim.x) g_perm_token[p] = 0;
}

// ---------------- stage 1: router (one warp per token) ----------------
__global__ __launch_bounds__(256) void router_kernel(const float* __restrict__ X,
                                                     const float* __restrict__ WR) {
    int warp = threadIdx.x >> 5, lane = threadIdx.x & 31;
    int t = blockIdx.x * 8 + warp;
    if (t >= T_TOK) return;

    float acc[8];
#pragma unroll
    for (int e = 0; e < 8; e++) acc[e] = 0.0f;

    const float* xr = X + (size_t)t * DM;
    for (int i = lane; i < DM; i += 32) {
        float xv = xr[i];
        const float4* w = reinterpret_cast<const float4*>(WR + (size_t)i * NEXP);
        float4 w0 = w[0], w1 = w[1];
        acc[0] += xv * w0.x; acc[1] += xv * w0.y; acc[2] += xv * w0.z; acc[3] += xv * w0.w;
        acc[4] += xv * w1.x; acc[5] += xv * w1.y; acc[6] += xv * w1.z; acc[7] += xv * w1.w;
    }
#pragma unroll
    for (int e = 0; e < 8; e++)
#pragma unroll
        for (int off = 16; off > 0; off >>= 1)
            acc[e] += __shfl_xor_sync(0xffffffffu, acc[e], off);

    if (lane == 0) {
        int i0 = 0; float v0 = acc[0];
#pragma unroll
        for (int e = 1; e < 8; e++) if (acc[e] > v0) { v0 = acc[e]; i0 = e; }
        int i1 = -1; float v1 = -3.4e38f;
#pragma unroll
        for (int e = 0; e < 8; e++) if (e != i0 && acc[e] > v1) { v1 = acc[e]; i1 = e; }
        // renormalized top-2 gates: softmax denominator cancels
        float r  = expf(v1 - v0);
        float g0 = 1.0f / (1.0f + r);
        float g1 = r / (1.0f + r);
        g_topk_idx[t * 2]      = i0;
        g_topk_idx[t * 2 + 1]  = i1;
        g_topk_gate[t * 2]     = g0;
        g_topk_gate[t * 2 + 1] = g1;
        atomicAdd(&g_counts[i0], 1);
        atomicAdd(&g_counts[i1], 1);
    }
}

// ---------------- stage 2: segment scan (128-aligned per expert) ----------------
__global__ void scan_kernel() {
    if (threadIdx.x == 0 && blockIdx.x == 0) {
        int s = 0;
        for (int e = 0; e < NEXP; e++) {
            g_seg[e] = s;
            g_cursor[e] = s;
            s += (g_counts[e] + BM - 1) & ~(BM - 1);
        }
        g_seg[NEXP] = s;
    }
}

// ---------------- stage 3: build permutation ----------------
__global__ void fill_kernel() {
    int i = blockIdx.x * blockDim.x + threadIdx.x;
    if (i >= T_TOK * 2) return;
    int e = g_topk_idx[i];
    int p = atomicAdd(&g_cursor[e], 1);
    g_perm_token[p] = i >> 1;
    g_inv[i] = p;
}

// ---------------- stage 4: fused SwiGLU up-projection GEMM ----------------
// ACT[rows, HID] = silu(Xg @ W1[e]) * (Xg @ W3[e])
// seg != null : grouped-by-expert with row gather via perm; seg == null : dense rows.
__global__ __launch_bounds__(256) void gemm1_kernel(
    const float* __restrict__ X,
    const int*   __restrict__ perm,
    const int*   __restrict__ seg,
    const float* __restrict__ W1,
    const float* __restrict__ W3,
    float*       __restrict__ ACT,
    int Mvalid) {
    __shared__ float As[BM][ASTR];
    __shared__ float B1s[KC][BSTR];
    __shared__ float B3s[KC][BSTR];

    int base = blockIdx.y * BM;
    int e = 0;
    if (seg) {
        int total = seg[NEXP];
        if (base >= total) return;
        while (seg[e + 1] <= base) e++;
    } else if (base >= Mvalid) {
        return;
    }
    const float* W1e = W1 + (size_t)e * DM * HID;
    const float* W3e = W3 + (size_t)e * DM * HID;
    int nb = blockIdx.x * BN;

    int tid = threadIdx.x, lane = tid & 31, warp = tid >> 5;
    int wm = warp & 3, wn = warp >> 2;          // 4x2 warps, warp tile 32x64
    int g = lane >> 2, tig = lane & 3;

    // A load mapping: 128 rows x 16 cols = 512 float4, 2 per thread
    int ar[2], ac[2];
    const float* aptr[2];
#pragma unroll
    for (int it = 0; it < 2; it++) {
        int pos = tid + 256 * it;
        int r = pos >> 2, j = pos & 3;
        ar[it] = r; ac[it] = j * 4;
        int row = base + r;
        int gr = perm ? perm[row] : row;
        aptr[it] = X + (size_t)gr * DM + ac[it];
    }

    float acc1[2][8][4], acc3[2][8][4];
#pragma unroll
    for (int mt = 0; mt < 2; mt++)
#pragma unroll
        for (int nt = 0; nt < 8; nt++)
#pragma unroll
            for (int q = 0; q < 4; q++) { acc1[mt][nt][q] = 0.0f; acc3[mt][nt][q] = 0.0f; }

    for (int kb = 0; kb < DM; kb += KC) {
        // load A tile (tf32-converted)
#pragma unroll
        for (int it = 0; it < 2; it++) {
            float4 v = *reinterpret_cast<const float4*>(aptr[it] + kb);
            float4 c;
            c.x = f2tf32(v.x); c.y = f2tf32(v.y); c.z = f2tf32(v.z); c.w = f2tf32(v.w);
            *reinterpret_cast<float4*>(&As[ar[it]][ac[it]]) = c;
        }
        // load B1/B3 tiles: kk = warp + 8*it, j = lane (coalesced)
#pragma unroll
        for (int it = 0; it < 2; it++) {
            int kk = warp + 8 * it;
            size_t rowoff = (size_t)(kb + kk);
            float4 v1 = *reinterpret_cast<const float4*>(W1e + rowoff * HID + nb + lane * 4);
            float4 v3 = *reinterpret_cast<const float4*>(W3e + rowoff * HID + nb + lane * 4);
            float4 c1, c3;
            c1.x = f2tf32(v1.x); c1.y = f2tf32(v1.y); c1.z = f2tf32(v1.z); c1.w = f2tf32(v1.w);
            c3.x = f2tf32(v3.x); c3.y = f2tf32(v3.y); c3.z = f2tf32(v3.z); c3.w = f2tf32(v3.w);
            *reinterpret_cast<float4*>(&B1s[kk][lane * 4]) = c1;
            *reinterpret_cast<float4*>(&B3s[kk][lane * 4]) = c3;
        }
        __syncthreads();

#pragma unroll
        for (int ks = 0; ks < 2; ks++) {
            int k8 = ks * 8;
            unsigned a[2][4];
#pragma unroll
            for (int mt = 0; mt < 2; mt++) {
                int rr = wm * 32 + mt * 16;
                a[mt][0] = __float_as_uint(As[rr + g][k8 + tig]);
                a[mt][1] = __float_as_uint(As[rr + g + 8][k8 + tig]);
                a[mt][2] = __float_as_uint(As[rr + g][k8 + tig + 4]);
                a[mt][3] = __float_as_uint(As[rr + g + 8][k8 + tig + 4]);
            }
            unsigned b1[8][2], b3[8][2];
#pragma unroll
            for (int nt = 0; nt < 8; nt++) {
                int cc = wn * 64 + nt * 8 + g;
                b1[nt][0] = __float_as_uint(B1s[k8 + tig][cc]);
                b1[nt][1] = __float_as_uint(B1s[k8 + tig + 4][cc]);
                b3[nt][0] = __float_as_uint(B3s[k8 + tig][cc]);
                b3[nt][1] = __float_as_uint(B3s[k8 + tig + 4][cc]);
            }
#pragma unroll
            for (int mt = 0; mt < 2; mt++)
#pragma unroll
                for (int nt = 0; nt < 8; nt++) {
                    mma_tf32(acc1[mt][nt], a[mt], b1[nt]);
                    mma_tf32(acc3[mt][nt], a[mt], b3[nt]);
                }
        }
        __syncthreads();
    }

    // epilogue: act = silu(h1) * h3
#pragma unroll
    for (int mt = 0; mt < 2; mt++) {
#pragma unroll
        for (int nt = 0; nt < 8; nt++) {
            int r0 = base + wm * 32 + mt * 16 + g;
            int c  = nb + wn * 64 + nt * 8 + tig * 2;
            float2 o0, o1;
            o0.x = silu_f(acc1[mt][nt][0]) * acc3[mt][nt][0];
            o0.y = silu_f(acc1[mt][nt][1]) * acc3[mt][nt][1];
            o1.x = silu_f(acc1[mt][nt][2]) * acc3[mt][nt][2];
            o1.y = silu_f(acc1[mt][nt][3]) * acc3[mt][nt][3];
            *reinterpret_cast<float2*>(ACT + (size_t)r0 * HID + c)       = o0;
            *reinterpret_cast<float2*>(ACT + (size_t)(r0 + 8) * HID + c) = o1;
        }
    }
}

// ---------------- stage 5: down-projection GEMM ----------------
// OUT[rows, DM] = A[rows, HID] @ W2[e]
__global__ __launch_bounds__(256) void gemm2_kernel(
    const float* __restrict__ A,
    const int*   __restrict__ seg,
    const float* __restrict__ W2,
    float*       __restrict__ OUT,
    int Mvalid) {
    __shared__ float As[BM][ASTR];
    __shared__ float Bs[KC][BSTR];

    int base = blockIdx.y * BM;
    int e = 0;
    if (seg) {
        int total = seg[NEXP];
        if (base >= total) return;
        while (seg[e + 1] <= base) e++;
    } else if (base >= Mvalid) {
        return;
    }
    const float* W2e = W2 + (size_t)e * HID * DM;
    int nb = blockIdx.x * BN;

    int tid = threadIdx.x, lane = tid & 31, warp = tid >> 5;
    int wm = warp & 3, wn = warp >> 2;
    int g = lane >> 2, tig = lane & 3;

    int ar[2], ac[2];
    const float* aptr[2];
#pragma unroll
    for (int it = 0; it < 2; it++) {
        int pos = tid + 256 * it;
        int r = pos >> 2, j = pos & 3;
        ar[it] = r; ac[it] = j * 4;
        aptr[it] = A + (size_t)(base + r) * HID + ac[it];
    }

    float acc[2][8][4];
#pragma unroll
    for (int mt = 0; mt < 2; mt++)
#pragma unroll
        for (int nt = 0; nt < 8; nt++)
#pragma unroll
            for (int q = 0; q < 4; q++) acc[mt][nt][q] = 0.0f;

    for (int kb = 0; kb < HID; kb += KC) {
#pragma unroll
        for (int it = 0; it < 2; it++) {
            float4 v = *reinterpret_cast<const float4*>(aptr[it] + kb);
            float4 c;
            c.x = f2tf32(v.x); c.y = f2tf32(v.y); c.z = f2tf32(v.z); c.w = f2tf32(v.w);
            *reinterpret_cast<float4*>(&As[ar[it]][ac[it]]) = c;
        }
#pragma unroll
        for (int it = 0; it < 2; it++) {
            int kk = warp + 8 * it;
            float4 v = *reinterpret_cast<const float4*>(W2e + (size_t)(kb + kk) * DM + nb + lane * 4);
            float4 c;
            c.x = f2tf32(v.x); c.y = f2tf32(v.y); c.z = f2tf32(v.z); c.w = f2tf32(v.w);
            *reinterpret_cast<float4*>(&Bs[kk][lane * 4]) = c;
        }
        __syncthreads();

#pragma unroll
        for (int ks = 0; ks < 2; ks++) {
            int k8 = ks * 8;
            unsigned a[2][4];
#pragma unroll
            for (int mt = 0; mt < 2; mt++) {
                int rr = wm * 32 + mt * 16;
                a[mt][0] = __float_as_uint(As[rr + g][k8 + tig]);
                a[mt][1] = __float_as_uint(As[rr + g + 8][k8 + tig]);
                a[mt][2] = __float_as_uint(As[rr + g][k8 + tig + 4]);
                a[mt][3] = __float_as_uint(As[rr + g + 8][k8 + tig + 4]);
            }
            unsigned b[8][2];
#pragma unroll
            for (int nt = 0; nt < 8; nt++) {
                int cc = wn * 64 + nt * 8 + g;
                b[nt][0] = __float_as_uint(Bs[k8 + tig][cc]);
                b[nt][1] = __float_as_uint(Bs[k8 + tig + 4][cc]);
            }
#pragma unroll
            for (int mt = 0; mt < 2; mt++)
#pragma unroll
                for (int nt = 0; nt < 8; nt++)
                    mma_tf32(acc[mt][nt], a[mt], b[nt]);
        }
        __syncthreads();
    }

#pragma unroll
    for (int mt = 0; mt < 2; mt++) {
#pragma unroll
        for (int nt = 0; nt < 8; nt++) {
            int r0 = base + wm * 32 + mt * 16 + g;
            int c  = nb + wn * 64 + nt * 8 + tig * 2;
            float2 o0, o1;
            o0.x = acc[mt][nt][0]; o0.y = acc[mt][nt][1];
            o1.x = acc[mt][nt][2]; o1.y = acc[mt][nt][3];
            *reinterpret_cast<float2*>(OUT + (size_t)r0 * DM + c)       = o0;
            *reinterpret_cast<float2*>(OUT + (size_t)(r0 + 8) * DM + c) = o1;
        }
    }
}

// ---------------- stage 6: combine routed contributions ----------------
__global__ void combine_kernel(float* __restrict__ OUT) {
    int i = blockIdx.x * blockDim.x + threadIdx.x;
    if (i >= T_TOK * DM) return;
    int t = i >> 10;          // DM = 1024
    int d = i & 1023;
    int p0 = g_inv[t * 2];
    int p1 = g_inv[t * 2 + 1];
    float v = OUT[i];
    v += g_topk_gate[t * 2]     * g_y[(size_t)p0 * DM + d];
    v += g_topk_gate[t * 2 + 1] * g_y[(size_t)p1 * DM + d];
    OUT[i] = v;
}

// ---------------- launch ----------------
extern "C" void kernel_launch(void* const* d_in, const int* in_sizes, int n_in,
                              void* d_out, int out_size) {
    (void)in_sizes; (void)n_in; (void)out_size;
    const float* x   = (const float*)d_in[0];
    const float* wr  = (const float*)d_in[1];
    const float* w1  = (const float*)d_in[2];
    const float* w3  = (const float*)d_in[3];
    const float* w2  = (const float*)d_in[4];
    const float* sw1 = (const float*)d_in[5];
    const float* sw3 = (const float*)d_in[6];
    const float* sw2 = (const float*)d_in[7];
    float* out = (float*)d_out;

    float *act, *yb, *shact;
    int *perm, *seg;
    cudaGetSymbolAddress((void**)&act,   g_act);
    cudaGetSymbolAddress((void**)&yb,    g_y);
    cudaGetSymbolAddress((void**)&shact, g_shact);
    cudaGetSymbolAddress((void**)&perm,  g_perm_token);
    cudaGetSymbolAddress((void**)&seg,   g_seg);

    reset_kernel<<<36, 256>>>();
    router_kernel<<<512, 256>>>(x, wr);
    scan_kernel<<<1, 32>>>();
    fill_kernel<<<32, 256>>>();

    // routed experts
    gemm1_kernel<<<dim3(HID / BN, PADMAX / BM), 256>>>(x, perm, seg, w1, w3, act, 0);
    gemm2_kernel<<<dim3(DM / BN, PADMAX / BM), 256>>>(act, seg, w2, yb, 0);

    // shared expert (writes d_out directly)
    gemm1_kernel<<<dim3(HID / BN, T_TOK / BM), 256>>>(x, nullptr, nullptr, sw1, sw3, shact, T_TOK);
    gemm2_kernel<<<dim3(DM / BN, T_TOK / BM), 256>>>(shact, nullptr, sw2, out, T_TOK);

    // add gated routed outputs
    combine_kernel<<<(T_TOK * DM) / 256, 256>>>(out);
}

// round 2
// speedup vs baseline: 1.2525x; 1.2525x over previous
#include <cuda_runtime.h>
#include <cstdint>

// Problem constants
#define T_TOK   4096
#define DM      1024
#define HID     2048
#define NEXP    8
#define PADMAX  9216        // 2*T + 8*128 worst-case expert padding

// GEMM tiling
#define BM 128
#define BN 128
#define KC 16
#define ASTR (KC + 4)       // 20  (conflict-free A-frag loads)
#define BSTR (BN + 8)       // 136 (conflict-free B-frag loads)
#define STAGES 3

#define SA (BM * ASTR)      // floats per A stage   (2560)
#define SB (KC * BSTR)      // floats per B stage   (2176)

// ---------------- scratch (device globals: allocation-free) ----------------
__device__ int   g_counts[NEXP];
__device__ int   g_seg[NEXP + 1];
__device__ int   g_cursor[NEXP];
__device__ int   g_topk_idx[T_TOK * 2];
__device__ float g_topk_gate[T_TOK * 2];
__device__ int   g_perm_token[PADMAX];
__device__ int   g_inv[T_TOK * 2];
__device__ float g_act[(size_t)PADMAX * HID];     // routed SwiGLU activations
__device__ float g_y[(size_t)PADMAX * DM];        // routed expert outputs
__device__ float g_shact[(size_t)T_TOK * HID];    // shared-expert activations

// ---------------- helpers ----------------
__device__ __forceinline__ unsigned tf32u(float x) {
    unsigned u;
    asm("cvt.rna.tf32.f32 %0, %1;" : "=r"(u) : "f"(x));
    return u;
}

__device__ __forceinline__ void mma_tf32(float* d, const unsigned* a, const unsigned* b) {
    asm volatile(
        "mma.sync.aligned.m16n8k8.row.col.f32.tf32.tf32.f32 "
        "{%0,%1,%2,%3}, {%4,%5,%6,%7}, {%8,%9}, {%0,%1,%2,%3};\n"
        : "+f"(d[0]), "+f"(d[1]), "+f"(d[2]), "+f"(d[3])
        : "r"(a[0]), "r"(a[1]), "r"(a[2]), "r"(a[3]), "r"(b[0]), "r"(b[1]));
}

__device__ __forceinline__ void cp_async16(float* smem_dst, const float* gmem_src) {
    unsigned s = (unsigned)__cvta_generic_to_shared(smem_dst);
    asm volatile("cp.async.cg.shared.global [%0], [%1], 16;\n" :: "r"(s), "l"(gmem_src));
}
__device__ __forceinline__ void cp_commit() {
    asm volatile("cp.async.commit_group;\n");
}
template <int N>
__device__ __forceinline__ void cp_wait() {
    asm volatile("cp.async.wait_group %0;\n" :: "n"(N));
}

__device__ __forceinline__ float silu_f(float h) {
    return __fdividef(h, 1.0f + __expf(-h));
}

// ---------------- stage 0: reset ----------------
__global__ void reset_kernel() {
    int i = blockIdx.x * blockDim.x + threadIdx.x;
    if (i < NEXP) g_counts[i] = 0;
    for (int p = i; p < PADMAX; p += gridDim.x * blockDim.x) g_perm_token[p] = 0;
}

// ---------------- stage 1: router (one warp per token) ----------------
__global__ __launch_bounds__(256) void router_kernel(const float* __restrict__ X,
                                                     const float* __restrict__ WR) {
    int warp = threadIdx.x >> 5, lane = threadIdx.x & 31;
    int t = blockIdx.x * 8 + warp;
    if (t >= T_TOK) return;

    float acc[8];
#pragma unroll
    for (int e = 0; e < 8; e++) acc[e] = 0.0f;

    const float* xr = X + (size_t)t * DM;
    for (int i = lane; i < DM; i += 32) {
        float xv = xr[i];
        const float4* w = reinterpret_cast<const float4*>(WR + (size_t)i * NEXP);
        float4 w0 = w[0], w1 = w[1];
        acc[0] += xv * w0.x; acc[1] += xv * w0.y; acc[2] += xv * w0.z; acc[3] += xv * w0.w;
        acc[4] += xv * w1.x; acc[5] += xv * w1.y; acc[6] += xv * w1.z; acc[7] += xv * w1.w;
    }
#pragma unroll
    for (int e = 0; e < 8; e++)
#pragma unroll
        for (int off = 16; off > 0; off >>= 1)
            acc[e] += __shfl_xor_sync(0xffffffffu, acc[e], off);

    if (lane == 0) {
        int i0 = 0; float v0 = acc[0];
#pragma unroll
        for (int e = 1; e < 8; e++) if (acc[e] > v0) { v0 = acc[e]; i0 = e; }
        int i1 = -1; float v1 = -3.4e38f;
#pragma unroll
        for (int e = 0; e < 8; e++) if (e != i0 && acc[e] > v1) { v1 = acc[e]; i1 = e; }
        float r  = expf(v1 - v0);
        float g0 = 1.0f / (1.0f + r);
        float g1 = r / (1.0f + r);
        g_topk_idx[t * 2]      = i0;
        g_topk_idx[t * 2 + 1]  = i1;
        g_topk_gate[t * 2]     = g0;
        g_topk_gate[t * 2 + 1] = g1;
        atomicAdd(&g_counts[i0], 1);
        atomicAdd(&g_counts[i1], 1);
    }
}

// ---------------- stage 2: segment scan (128-aligned per expert) ----------------
__global__ void scan_kernel() {
    if (threadIdx.x == 0 && blockIdx.x == 0) {
        int s = 0;
        for (int e = 0; e < NEXP; e++) {
            g_seg[e] = s;
            g_cursor[e] = s;
            s += (g_counts[e] + BM - 1) & ~(BM - 1);
        }
        g_seg[NEXP] = s;
    }
}

// ---------------- stage 3: build permutation ----------------
__global__ void fill_kernel() {
    int i = blockIdx.x * blockDim.x + threadIdx.x;
    if (i >= T_TOK * 2) return;
    int e = g_topk_idx[i];
    int p = atomicAdd(&g_cursor[e], 1);
    g_perm_token[p] = i >> 1;
    g_inv[i] = p;
}

// ---------------- stage 4: fused SwiGLU up-projection GEMM ----------------
// ACT[rows, HID] = silu(Xg @ W1[e]) * (Xg @ W3[e])
// 3-stage cp.async pipeline; fp32 in smem, tf32-convert on fragment load.
__global__ __launch_bounds__(256) void gemm1_kernel(
    const float* __restrict__ X,
    const int*   __restrict__ perm,
    const int*   __restrict__ seg,
    const float* __restrict__ W1,
    const float* __restrict__ W3,
    float*       __restrict__ ACT,
    int Mvalid) {
    extern __shared__ float sm[];
    float* As = sm;                    // STAGES * SA
    float* B1s = sm + STAGES * SA;     // STAGES * SB
    float* B3s = B1s + STAGES * SB;    // STAGES * SB

    int base = blockIdx.y * BM;
    int e = 0;
    if (seg) {
        int total = seg[NEXP];
        if (base >= total) return;
        while (seg[e + 1] <= base) e++;
    } else if (base >= Mvalid) {
        return;
    }
    const float* W1e = W1 + (size_t)e * DM * HID;
    const float* W3e = W3 + (size_t)e * DM * HID;
    int nb = blockIdx.x * BN;

    int tid = threadIdx.x, lane = tid & 31, warp = tid >> 5;
    int wm = warp & 3, wn = warp >> 2;          // 4x2 warps, warp tile 32x64
    int g = lane >> 2, tig = lane & 3;

    // A load mapping: 128 rows x 16 cols = 512 float4, 2 per thread
    int ar[2], ac[2];
    const float* aptr[2];
#pragma unroll
    for (int it = 0; it < 2; it++) {
        int pos = tid + 256 * it;
        int r = pos >> 2, j = pos & 3;
        ar[it] = r; ac[it] = j * 4;
        int row = base + r;
        int gr = perm ? perm[row] : row;
        aptr[it] = X + (size_t)gr * DM + ac[it];
    }

    float acc1[2][8][4], acc3[2][8][4];
#pragma unroll
    for (int mt = 0; mt < 2; mt++)
#pragma unroll
        for (int nt = 0; nt < 8; nt++)
#pragma unroll
            for (int q = 0; q < 4; q++) { acc1[mt][nt][q] = 0.0f; acc3[mt][nt][q] = 0.0f; }

    const int iters = DM / KC;   // 64

    // issue loads for k-slice `k` into stage `st`
    auto issue = [&](int k, int st) {
        int kb = k * KC;
#pragma unroll
        for (int it = 0; it < 2; it++)
            cp_async16(&As[st * SA + ar[it] * ASTR + ac[it]], aptr[it] + kb);
#pragma unroll
        for (int it = 0; it < 2; it++) {
            int kk = warp + 8 * it;
            size_t rowoff = (size_t)(kb + kk);
            cp_async16(&B1s[st * SB + kk * BSTR + lane * 4], W1e + rowoff * HID + nb + lane * 4);
            cp_async16(&B3s[st * SB + kk * BSTR + lane * 4], W3e + rowoff * HID + nb + lane * 4);
        }
        cp_commit();
    };

    issue(0, 0);
    issue(1, 1);

    int st = 0;
    for (int k = 0; k < iters; k++) {
        if (k + 1 < iters) cp_wait<1>(); else cp_wait<0>();
        __syncthreads();
        if (k + 2 < iters) issue(k + 2, (k + 2) % STAGES);

        const float* Ast = As + st * SA;
        const float* B1t = B1s + st * SB;
        const float* B3t = B3s + st * SB;
#pragma unroll
        for (int ks = 0; ks < 2; ks++) {
            int k8 = ks * 8;
            unsigned a[2][4];
#pragma unroll
            for (int mt = 0; mt < 2; mt++) {
                int rr = wm * 32 + mt * 16;
                a[mt][0] = tf32u(Ast[(rr + g) * ASTR + k8 + tig]);
                a[mt][1] = tf32u(Ast[(rr + g + 8) * ASTR + k8 + tig]);
                a[mt][2] = tf32u(Ast[(rr + g) * ASTR + k8 + tig + 4]);
                a[mt][3] = tf32u(Ast[(rr + g + 8) * ASTR + k8 + tig + 4]);
            }
            unsigned b1[8][2], b3[8][2];
#pragma unroll
            for (int nt = 0; nt < 8; nt++) {
                int cc = wn * 64 + nt * 8 + g;
                b1[nt][0] = tf32u(B1t[(k8 + tig) * BSTR + cc]);
                b1[nt][1] = tf32u(B1t[(k8 + tig + 4) * BSTR + cc]);
                b3[nt][0] = tf32u(B3t[(k8 + tig) * BSTR + cc]);
                b3[nt][1] = tf32u(B3t[(k8 + tig + 4) * BSTR + cc]);
            }
#pragma unroll
            for (int mt = 0; mt < 2; mt++)
#pragma unroll
                for (int nt = 0; nt < 8; nt++) {
                    mma_tf32(acc1[mt][nt], a[mt], b1[nt]);
                    mma_tf32(acc3[mt][nt], a[mt], b3[nt]);
                }
        }
        st = (st == STAGES - 1) ? 0 : st + 1;
    }

    // epilogue: act = silu(h1) * h3
#pragma unroll
    for (int mt = 0; mt < 2; mt++) {
#pragma unroll
        for (int nt = 0; nt < 8; nt++) {
            int r0 = base + wm * 32 + mt * 16 + g;
            int c  = nb + wn * 64 + nt * 8 + tig * 2;
            float2 o0, o1;
            o0.x = silu_f(acc1[mt][nt][0]) * acc3[mt][nt][0];
            o0.y = silu_f(acc1[mt][nt][1]) * acc3[mt][nt][1];
            o1.x = silu_f(acc1[mt][nt][2]) * acc3[mt][nt][2];
            o1.y = silu_f(acc1[mt][nt][3]) * acc3[mt][nt][3];
            *reinterpret_cast<float2*>(ACT + (size_t)r0 * HID + c)       = o0;
            *reinterpret_cast<float2*>(ACT + (size_t)(r0 + 8) * HID + c) = o1;
        }
    }
}

// ---------------- stage 5: down-projection GEMM ----------------
// OUT[rows, DM] = A[rows, HID] @ W2[e]
__global__ __launch_bounds__(256) void gemm2_kernel(
    const float* __restrict__ A,
    const int*   __restrict__ seg,
    const float* __restrict__ W2,
    float*       __restrict__ OUT,
    int Mvalid) {
    extern __shared__ float sm[];
    float* As = sm;                  // STAGES * SA
    float* Bs = sm + STAGES * SA;    // STAGES * SB

    int base = blockIdx.y * BM;
    int e = 0;
    if (seg) {
        int total = seg[NEXP];
        if (base >= total) return;
        while (seg[e + 1] <= base) e++;
    } else if (base >= Mvalid) {
        return;
    }
    const float* W2e = W2 + (size_t)e * HID * DM;
    int nb = blockIdx.x * BN;

    int tid = threadIdx.x, lane = tid & 31, warp = tid >> 5;
    int wm = warp & 3, wn = warp >> 2;
    int g = lane >> 2, tig = lane & 3;

    int ar[2], ac[2];
    const float* aptr[2];
#pragma unroll
    for (int it = 0; it < 2; it++) {
        int pos = tid + 256 * it;
        int r = pos >> 2, j = pos & 3;
        ar[it] = r; ac[it] = j * 4;
        aptr[it] = A + (size_t)(base + r) * HID + ac[it];
    }

    float acc[2][8][4];
#pragma unroll
    for (int mt = 0; mt < 2; mt++)
#pragma unroll
        for (int nt = 0; nt < 8; nt++)
#pragma unroll
            for (int q = 0; q < 4; q++) acc[mt][nt][q] = 0.0f;

    const int iters = HID / KC;   // 128

    auto issue = [&](int k, int st) {
        int kb = k * KC;
#pragma unroll
        for (int it = 0; it < 2; it++)
            cp_async16(&As[st * SA + ar[it] * ASTR + ac[it]], aptr[it] + kb);
#pragma unroll
        for (int it = 0; it < 2; it++) {
            int kk = warp + 8 * it;
            cp_async16(&Bs[st * SB + kk * BSTR + lane * 4],
                       W2e + (size_t)(kb + kk) * DM + nb + lane * 4);
        }
        cp_commit();
    };

    issue(0, 0);
    issue(1, 1);

    int st = 0;
    for (int k = 0; k < iters; k++) {
        if (k + 1 < iters) cp_wait<1>(); else cp_wait<0>();
        __syncthreads();
        if (k + 2 < iters) issue(k + 2, (k + 2) % STAGES);

        const float* Ast = As + st * SA;
        const float* Bt  = Bs + st * SB;
#pragma unroll
        for (int ks = 0; ks < 2; ks++) {
            int k8 = ks * 8;
            unsigned a[2][4];
#pragma unroll
            for (int mt = 0; mt < 2; mt++) {
                int rr = wm * 32 + mt * 16;
                a[mt][0] = tf32u(Ast[(rr + g) * ASTR + k8 + tig]);
                a[mt][1] = tf32u(Ast[(rr + g + 8) * ASTR + k8 + tig]);
                a[mt][2] = tf32u(Ast[(rr + g) * ASTR + k8 + tig + 4]);
                a[mt][3] = tf32u(Ast[(rr + g + 8) * ASTR + k8 + tig + 4]);
            }
            unsigned b[8][2];
#pragma unroll
            for (int nt = 0; nt < 8; nt++) {
                int cc = wn * 64 + nt * 8 + g;
                b[nt][0] = tf32u(Bt[(k8 + tig) * BSTR + cc]);
                b[nt][1] = tf32u(Bt[(k8 + tig + 4) * BSTR + cc]);
            }
#pragma unroll
            for (int mt = 0; mt < 2; mt++)
#pragma unroll
                for (int nt = 0; nt < 8; nt++)
                    mma_tf32(acc[mt][nt], a[mt], b[nt]);
        }
        st = (st == STAGES - 1) ? 0 : st + 1;
    }

#pragma unroll
    for (int mt = 0; mt < 2; mt++) {
#pragma unroll
        for (int nt = 0; nt < 8; nt++) {
            int r0 = base + wm * 32 + mt * 16 + g;
            int c  = nb + wn * 64 + nt * 8 + tig * 2;
            float2 o0, o1;
            o0.x = acc[mt][nt][0]; o0.y = acc[mt][nt][1];
            o1.x = acc[mt][nt][2]; o1.y = acc[mt][nt][3];
            *reinterpret_cast<float2*>(OUT + (size_t)r0 * DM + c)       = o0;
            *reinterpret_cast<float2*>(OUT + (size_t)(r0 + 8) * DM + c) = o1;
        }
    }
}

// ---------------- stage 6: combine routed contributions ----------------
__global__ void combine_kernel(float* __restrict__ OUT) {
    int i = blockIdx.x * blockDim.x + threadIdx.x;
    if (i >= T_TOK * DM) return;
    int t = i >> 10;          // DM = 1024
    int d = i & 1023;
    int p0 = g_inv[t * 2];
    int p1 = g_inv[t * 2 + 1];
    float v = OUT[i];
    v += g_topk_gate[t * 2]     * g_y[(size_t)p0 * DM + d];
    v += g_topk_gate[t * 2 + 1] * g_y[(size_t)p1 * DM + d];
    OUT[i] = v;
}

// ---------------- launch ----------------
#define G1_SMEM ((STAGES * SA + 2 * STAGES * SB) * 4)   // 82944 bytes
#define G2_SMEM ((STAGES * SA + STAGES * SB) * 4)       // 56832 bytes

extern "C" void kernel_launch(void* const* d_in, const int* in_sizes, int n_in,
                              void* d_out, int out_size) {
    (void)in_sizes; (void)n_in; (void)out_size;
    const float* x   = (const float*)d_in[0];
    const float* wr  = (const float*)d_in[1];
    const float* w1  = (const float*)d_in[2];
    const float* w3  = (const float*)d_in[3];
    const float* w2  = (const float*)d_in[4];
    const float* sw1 = (const float*)d_in[5];
    const float* sw3 = (const float*)d_in[6];
    const float* sw2 = (const float*)d_in[7];
    float* out = (float*)d_out;

    float *act, *yb, *shact;
    int *perm, *seg;
    cudaGetSymbolAddress((void**)&act,   g_act);
    cudaGetSymbolAddress((void**)&yb,    g_y);
    cudaGetSymbolAddress((void**)&shact, g_shact);
    cudaGetSymbolAddress((void**)&perm,  g_perm_token);
    cudaGetSymbolAddress((void**)&seg,   g_seg);

    cudaFuncSetAttribute(gemm1_kernel, cudaFuncAttributeMaxDynamicSharedMemorySize, G1_SMEM);
    cudaFuncSetAttribute(gemm2_kernel, cudaFuncAttributeMaxDynamicSharedMemorySize, G2_SMEM);

    reset_kernel<<<36, 256>>>();
    router_kernel<<<512, 256>>>(x, wr);
    scan_kernel<<<1, 32>>>();
    fill_kernel<<<32, 256>>>();

    // routed experts
    gemm1_kernel<<<dim3(HID / BN, PADMAX / BM), 256, G1_SMEM>>>(x, perm, seg, w1, w3, act, 0);
    gemm2_kernel<<<dim3(DM / BN, PADMAX / BM), 256, G2_SMEM>>>(act, seg, w2, yb, 0);

    // shared expert (writes d_out directly)
    gemm1_kernel<<<dim3(HID / BN, T_TOK / BM), 256, G1_SMEM>>>(x, nullptr, nullptr, sw1, sw3, shact, T_TOK);
    gemm2_kernel<<<dim3(DM / BN, T_TOK / BM), 256, G2_SMEM>>>(shact, nullptr, sw2, out, T_TOK);

    // add gated routed outputs
    combine_kernel<<<(T_TOK * DM) / 256, 256>>>(out);
}

// round 3
// speedup vs baseline: 1.4613x; 1.1667x over previous
#include <cuda_runtime.h>
#include <cstdint>

// Problem constants
#define T_TOK   4096
#define DM      1024
#define HID     2048
#define NEXP    8
#define PADMAX  9216                 // routed rows upper bound (2*T + 8*127 pad)
#define MAXROWS (PADMAX + T_TOK)     // + shared-expert segment (13312)

// GEMM tiling
#define BM 128
#define BN 128
#define KC 32
#define ASTR (KC + 4)       // 36  (conflict-free A-frag loads: 36 mod 32 = 4)
#define BSTR (BN + 8)       // 136 (conflict-free B-frag loads: 136 mod 32 = 8)
#define STAGES 3

#define SA (BM * ASTR)      // floats per A stage   (4608)
#define SB (KC * BSTR)      // floats per B stage   (4352)

// ---------------- scratch (device globals: allocation-free) ----------------
__device__ int   g_counts[NEXP];
__device__ int   g_seg[NEXP + 2];    // 9 segments: 8 routed + 1 shared
__device__ int   g_cursor[NEXP];
__device__ int   g_topk_idx[T_TOK * 2];
__device__ float g_topk_gate[T_TOK * 2];
__device__ int   g_perm_token[MAXROWS];
__device__ int   g_inv[T_TOK * 2];
__device__ float g_act[(size_t)MAXROWS * HID];    // SwiGLU activations (all segments)
__device__ float g_y[(size_t)MAXROWS * DM];       // expert outputs (all segments)

// ---------------- helpers ----------------
__device__ __forceinline__ unsigned tf32u(float x) {
    unsigned u;
    asm("cvt.rna.tf32.f32 %0, %1;" : "=r"(u) : "f"(x));
    return u;
}

__device__ __forceinline__ void mma_tf32(float* d, const unsigned* a, const unsigned* b) {
    asm volatile(
        "mma.sync.aligned.m16n8k8.row.col.f32.tf32.tf32.f32 "
        "{%0,%1,%2,%3}, {%4,%5,%6,%7}, {%8,%9}, {%0,%1,%2,%3};\n"
        : "+f"(d[0]), "+f"(d[1]), "+f"(d[2]), "+f"(d[3])
        : "r"(a[0]), "r"(a[1]), "r"(a[2]), "r"(a[3]), "r"(b[0]), "r"(b[1]));
}

__device__ __forceinline__ void cp_async16(float* smem_dst, const float* gmem_src) {
    unsigned s = (unsigned)__cvta_generic_to_shared(smem_dst);
    asm volatile("cp.async.cg.shared.global [%0], [%1], 16;\n" :: "r"(s), "l"(gmem_src));
}
__device__ __forceinline__ void cp_commit() {
    asm volatile("cp.async.commit_group;\n");
}
template <int N>
__device__ __forceinline__ void cp_wait() {
    asm volatile("cp.async.wait_group %0;\n" :: "n"(N));
}

__device__ __forceinline__ float silu_f(float h) {
    return __fdividef(h, 1.0f + __expf(-h));
}

// ---------------- stage 0: reset ----------------
__global__ void reset_kernel() {
    int i = blockIdx.x * blockDim.x + threadIdx.x;
    if (i < NEXP) g_counts[i] = 0;
    for (int p = i; p < MAXROWS; p += gridDim.x * blockDim.x) g_perm_token[p] = 0;
}

// ---------------- stage 1: router (one warp per token) ----------------
__global__ __launch_bounds__(256) void router_kernel(const float* __restrict__ X,
                                                     const float* __restrict__ WR) {
    int warp = threadIdx.x >> 5, lane = threadIdx.x & 31;
    int t = blockIdx.x * 8 + warp;
    if (t >= T_TOK) return;

    float acc[8];
#pragma unroll
    for (int e = 0; e < 8; e++) acc[e] = 0.0f;

    const float* xr = X + (size_t)t * DM;
    for (int i = lane; i < DM; i += 32) {
        float xv = xr[i];
        const float4* w = reinterpret_cast<const float4*>(WR + (size_t)i * NEXP);
        float4 w0 = w[0], w1 = w[1];
        acc[0] += xv * w0.x; acc[1] += xv * w0.y; acc[2] += xv * w0.z; acc[3] += xv * w0.w;
        acc[4] += xv * w1.x; acc[5] += xv * w1.y; acc[6] += xv * w1.z; acc[7] += xv * w1.w;
    }
#pragma unroll
    for (int e = 0; e < 8; e++)
#pragma unroll
        for (int off = 16; off > 0; off >>= 1)
            acc[e] += __shfl_xor_sync(0xffffffffu, acc[e], off);

    if (lane == 0) {
        int i0 = 0; float v0 = acc[0];
#pragma unroll
        for (int e = 1; e < 8; e++) if (acc[e] > v0) { v0 = acc[e]; i0 = e; }
        int i1 = -1; float v1 = -3.4e38f;
#pragma unroll
        for (int e = 0; e < 8; e++) if (e != i0 && acc[e] > v1) { v1 = acc[e]; i1 = e; }
        float r  = expf(v1 - v0);
        float g0 = 1.0f / (1.0f + r);
        float g1 = r / (1.0f + r);
        g_topk_idx[t * 2]      = i0;
        g_topk_idx[t * 2 + 1]  = i1;
        g_topk_gate[t * 2]     = g0;
        g_topk_gate[t * 2 + 1] = g1;
        atomicAdd(&g_counts[i0], 1);
        atomicAdd(&g_counts[i1], 1);
    }
}

// ---------------- stage 2: segment scan (128-aligned; segment 8 = shared) ----------------
__global__ void scan_kernel() {
    if (threadIdx.x == 0 && blockIdx.x == 0) {
        int s = 0;
        for (int e = 0; e < NEXP; e++) {
            g_seg[e] = s;
            g_cursor[e] = s;
            s += (g_counts[e] + BM - 1) & ~(BM - 1);
        }
        g_seg[NEXP] = s;              // shared segment start
        g_seg[NEXP + 1] = s + T_TOK;  // total rows
    }
}

// ---------------- stage 3: build permutation (routed + shared identity) ----------------
__global__ void fill_kernel() {
    int i = blockIdx.x * blockDim.x + threadIdx.x;
    if (i < T_TOK * 2) {
        int e = g_topk_idx[i];
        int p = atomicAdd(&g_cursor[e], 1);
        g_perm_token[p] = i >> 1;
        g_inv[i] = p;
    } else if (i < T_TOK * 3) {
        int t = i - T_TOK * 2;
        g_perm_token[g_seg[NEXP] + t] = t;   // shared-expert rows: identity
    }
}

// ---------------- stage 4: fused SwiGLU up-projection grouped GEMM ----------------
// ACT[rows, HID] = silu(Xg @ W1[e]) * (Xg @ W3[e]); segment 8 uses SW1/SW3.
__global__ __launch_bounds__(256) void gemm1_kernel(
    const float* __restrict__ X,
    const float* __restrict__ W1,
    const float* __restrict__ W3,
    const float* __restrict__ SW1,
    const float* __restrict__ SW3,
    float*       __restrict__ ACT) {
    extern __shared__ float sm[];
    float* As  = sm;                   // STAGES * SA
    float* B1s = sm + STAGES * SA;     // STAGES * SB
    float* B3s = B1s + STAGES * SB;    // STAGES * SB

    int base = blockIdx.y * BM;
    int total = g_seg[NEXP + 1];
    if (base >= total) return;
    int e = 0;
    while (g_seg[e + 1] <= base) e++;

    const float* W1e = (e < NEXP) ? W1 + (size_t)e * DM * HID : SW1;
    const float* W3e = (e < NEXP) ? W3 + (size_t)e * DM * HID : SW3;
    int nb = blockIdx.x * BN;

    int tid = threadIdx.x, lane = tid & 31, warp = tid >> 5;
    int wm = warp & 3, wn = warp >> 2;          // 4x2 warps, warp tile 32x64
    int g = lane >> 2, tig = lane & 3;

    // A load mapping: 128 rows x 32 cols = 1024 float4, 4 per thread
    int ar[4], ac[4];
    const float* aptr[4];
#pragma unroll
    for (int it = 0; it < 4; it++) {
        int pos = tid + 256 * it;
        int r = pos >> 3, j = pos & 7;
        ar[it] = r; ac[it] = j * 4;
        int gr = g_perm_token[base + r];
        aptr[it] = X + (size_t)gr * DM + ac[it];
    }

    float acc1[2][8][4], acc3[2][8][4];
#pragma unroll
    for (int mt = 0; mt < 2; mt++)
#pragma unroll
        for (int nt = 0; nt < 8; nt++)
#pragma unroll
            for (int q = 0; q < 4; q++) { acc1[mt][nt][q] = 0.0f; acc3[mt][nt][q] = 0.0f; }

    const int iters = DM / KC;   // 32

    auto issue = [&](int k, int st) {
        int kb = k * KC;
#pragma unroll
        for (int it = 0; it < 4; it++)
            cp_async16(&As[st * SA + ar[it] * ASTR + ac[it]], aptr[it] + kb);
#pragma unroll
        for (int it = 0; it < 4; it++) {
            int kk = warp + 8 * it;
            size_t rowoff = (size_t)(kb + kk);
            cp_async16(&B1s[st * SB + kk * BSTR + lane * 4], W1e + rowoff * HID + nb + lane * 4);
            cp_async16(&B3s[st * SB + kk * BSTR + lane * 4], W3e + rowoff * HID + nb + lane * 4);
        }
        cp_commit();
    };

    issue(0, 0);
    issue(1, 1);

    int st = 0;
    for (int k = 0; k < iters; k++) {
        if (k + 1 < iters) cp_wait<1>(); else cp_wait<0>();
        __syncthreads();
        if (k + 2 < iters) issue(k + 2, (k + 2) % STAGES);

        const float* Ast = As + st * SA;
        const float* B1t = B1s + st * SB;
        const float* B3t = B3s + st * SB;
#pragma unroll
        for (int ks = 0; ks < 4; ks++) {
            int k8 = ks * 8;
            unsigned a[2][4];
#pragma unroll
            for (int mt = 0; mt < 2; mt++) {
                int rr = wm * 32 + mt * 16;
                a[mt][0] = tf32u(Ast[(rr + g) * ASTR + k8 + tig]);
                a[mt][1] = tf32u(Ast[(rr + g + 8) * ASTR + k8 + tig]);
                a[mt][2] = tf32u(Ast[(rr + g) * ASTR + k8 + tig + 4]);
                a[mt][3] = tf32u(Ast[(rr + g + 8) * ASTR + k8 + tig + 4]);
            }
            unsigned b1[8][2], b3[8][2];
#pragma unroll
            for (int nt = 0; nt < 8; nt++) {
                int cc = wn * 64 + nt * 8 + g;
                b1[nt][0] = tf32u(B1t[(k8 + tig) * BSTR + cc]);
                b1[nt][1] = tf32u(B1t[(k8 + tig + 4) * BSTR + cc]);
                b3[nt][0] = tf32u(B3t[(k8 + tig) * BSTR + cc]);
                b3[nt][1] = tf32u(B3t[(k8 + tig + 4) * BSTR + cc]);
            }
#pragma unroll
            for (int mt = 0; mt < 2; mt++)
#pragma unroll
                for (int nt = 0; nt < 8; nt++) {
                    mma_tf32(acc1[mt][nt], a[mt], b1[nt]);
                    mma_tf32(acc3[mt][nt], a[mt], b3[nt]);
                }
        }
        st = (st == STAGES - 1) ? 0 : st + 1;
    }

    // epilogue: act = silu(h1) * h3
#pragma unroll
    for (int mt = 0; mt < 2; mt++) {
#pragma unroll
        for (int nt = 0; nt < 8; nt++) {
            int r0 = base + wm * 32 + mt * 16 + g;
            int c  = nb + wn * 64 + nt * 8 + tig * 2;
            float2 o0, o1;
            o0.x = silu_f(acc1[mt][nt][0]) * acc3[mt][nt][0];
            o0.y = silu_f(acc1[mt][nt][1]) * acc3[mt][nt][1];
            o1.x = silu_f(acc1[mt][nt][2]) * acc3[mt][nt][2];
            o1.y = silu_f(acc1[mt][nt][3]) * acc3[mt][nt][3];
            *reinterpret_cast<float2*>(ACT + (size_t)r0 * HID + c)       = o0;
            *reinterpret_cast<float2*>(ACT + (size_t)(r0 + 8) * HID + c) = o1;
        }
    }
}

// ---------------- stage 5: down-projection grouped GEMM ----------------
// Y[rows, DM] = ACT[rows, HID] @ W2[e]; segment 8 uses SW2.
__global__ __launch_bounds__(256) void gemm2_kernel(
    const float* __restrict__ A,
    const float* __restrict__ W2,
    const float* __restrict__ SW2,
    float*       __restrict__ OUT) {
    extern __shared__ float sm[];
    float* As = sm;                  // STAGES * SA
    float* Bs = sm + STAGES * SA;    // STAGES * SB

    int base = blockIdx.y * BM;
    int total = g_seg[NEXP + 1];
    if (base >= total) return;
    int e = 0;
    while (g_seg[e + 1] <= base) e++;

    const float* W2e = (e < NEXP) ? W2 + (size_t)e * HID * DM : SW2;
    int nb = blockIdx.x * BN;

    int tid = threadIdx.x, lane = tid & 31, warp = tid >> 5;
    int wm = warp & 3, wn = warp >> 2;
    int g = lane >> 2, tig = lane & 3;

    int ar[4], ac[4];
    const float* aptr[4];
#pragma unroll
    for (int it = 0; it < 4; it++) {
        int pos = tid + 256 * it;
        int r = pos >> 3, j = pos & 7;
        ar[it] = r; ac[it] = j * 4;
        aptr[it] = A + (size_t)(base + r) * HID + ac[it];
    }

    float acc[2][8][4];
#pragma unroll
    for (int mt = 0; mt < 2; mt++)
#pragma unroll
        for (int nt = 0; nt < 8; nt++)
#pragma unroll
            for (int q = 0; q < 4; q++) acc[mt][nt][q] = 0.0f;

    const int iters = HID / KC;   // 64

    auto issue = [&](int k, int st) {
        int kb = k * KC;
#pragma unroll
        for (int it = 0; it < 4; it++)
            cp_async16(&As[st * SA + ar[it] * ASTR + ac[it]], aptr[it] + kb);
#pragma unroll
        for (int it = 0; it < 4; it++) {
            int kk = warp + 8 * it;
            cp_async16(&Bs[st * SB + kk * BSTR + lane * 4],
                       W2e + (size_t)(kb + kk) * DM + nb + lane * 4);
        }
        cp_commit();
    };

    issue(0, 0);
    issue(1, 1);

    int st = 0;
    for (int k = 0; k < iters; k++) {
        if (k + 1 < iters) cp_wait<1>(); else cp_wait<0>();
        __syncthreads();
        if (k + 2 < iters) issue(k + 2, (k + 2) % STAGES);

        const float* Ast = As + st * SA;
        const float* Bt  = Bs + st * SB;
#pragma unroll
        for (int ks = 0; ks < 4; ks++) {
            int k8 = ks * 8;
            unsigned a[2][4];
#pragma unroll
            for (int mt = 0; mt < 2; mt++) {
                int rr = wm * 32 + mt * 16;
                a[mt][0] = tf32u(Ast[(rr + g) * ASTR + k8 + tig]);
                a[mt][1] = tf32u(Ast[(rr + g + 8) * ASTR + k8 + tig]);
                a[mt][2] = tf32u(Ast[(rr + g) * ASTR + k8 + tig + 4]);
                a[mt][3] = tf32u(Ast[(rr + g + 8) * ASTR + k8 + tig + 4]);
            }
            unsigned b[8][2];
#pragma unroll
            for (int nt = 0; nt < 8; nt++) {
                int cc = wn * 64 + nt * 8 + g;
                b[nt][0] = tf32u(Bt[(k8 + tig) * BSTR + cc]);
                b[nt][1] = tf32u(Bt[(k8 + tig + 4) * BSTR + cc]);
            }
#pragma unroll
            for (int mt = 0; mt < 2; mt++)
#pragma unroll
                for (int nt = 0; nt < 8; nt++)
                    mma_tf32(acc[mt][nt], a[mt], b[nt]);
        }
        st = (st == STAGES - 1) ? 0 : st + 1;
    }

#pragma unroll
    for (int mt = 0; mt < 2; mt++) {
#pragma unroll
        for (int nt = 0; nt < 8; nt++) {
            int r0 = base + wm * 32 + mt * 16 + g;
            int c  = nb + wn * 64 + nt * 8 + tig * 2;
            float2 o0, o1;
            o0.x = acc[mt][nt][0]; o0.y = acc[mt][nt][1];
            o1.x = acc[mt][nt][2]; o1.y = acc[mt][nt][3];
            *reinterpret_cast<float2*>(OUT + (size_t)r0 * DM + c)       = o0;
            *reinterpret_cast<float2*>(OUT + (size_t)(r0 + 8) * DM + c) = o1;
        }
    }
}

// ---------------- stage 6: combine shared + gated routed ----------------
__global__ void combine_kernel(float* __restrict__ OUT) {
    int i = blockIdx.x * blockDim.x + threadIdx.x;
    if (i >= T_TOK * DM) return;
    int t = i >> 10;          // DM = 1024
    int d = i & 1023;
    int s8 = g_seg[NEXP];
    int p0 = g_inv[t * 2];
    int p1 = g_inv[t * 2 + 1];
    float v = g_y[(size_t)(s8 + t) * DM + d];
    v += g_topk_gate[t * 2]     * g_y[(size_t)p0 * DM + d];
    v += g_topk_gate[t * 2 + 1] * g_y[(size_t)p1 * DM + d];
    OUT[i] = v;
}

// ---------------- launch ----------------
#define G1_SMEM ((STAGES * SA + 2 * STAGES * SB) * 4)   // 157440 bytes
#define G2_SMEM ((STAGES * SA + STAGES * SB) * 4)       // 105216 bytes

extern "C" void kernel_launch(void* const* d_in, const int* in_sizes, int n_in,
                              void* d_out, int out_size) {
    (void)in_sizes; (void)n_in; (void)out_size;
    const float* x   = (const float*)d_in[0];
    const float* wr  = (const float*)d_in[1];
    const float* w1  = (const float*)d_in[2];
    const float* w3  = (const float*)d_in[3];
    const float* w2  = (const float*)d_in[4];
    const float* sw1 = (const float*)d_in[5];
    const float* sw3 = (const float*)d_in[6];
    const float* sw2 = (const float*)d_in[7];
    float* out = (float*)d_out;

    float *act, *yb;
    cudaGetSymbolAddress((void**)&act, g_act);
    cudaGetSymbolAddress((void**)&yb,  g_y);

    cudaFuncSetAttribute(gemm1_kernel, cudaFuncAttributeMaxDynamicSharedMemorySize, G1_SMEM);
    cudaFuncSetAttribute(gemm2_kernel, cudaFuncAttributeMaxDynamicSharedMemorySize, G2_SMEM);

    reset_kernel<<<52, 256>>>();
    router_kernel<<<512, 256>>>(x, wr);
    scan_kernel<<<1, 32>>>();
    fill_kernel<<<48, 256>>>();

    // all experts (8 routed segments + shared segment) in two grouped GEMMs
    gemm1_kernel<<<dim3(HID / BN, MAXROWS / BM), 256, G1_SMEM>>>(x, w1, w3, sw1, sw3, act);
    gemm2_kernel<<<dim3(DM / BN, MAXROWS / BM), 256, G2_SMEM>>>(act, w2, sw2, yb);

    // final combine writes d_out
    combine_kernel<<<(T_TOK * DM) / 256, 256>>>(out);
}

// round 4
// speedup vs baseline: 2.3130x; 1.5828x over previous
#include <cuda_runtime.h>
#include <cuda_fp16.h>
#include <cstdint>

// Problem constants
#define T_TOK   4096
#define DM      1024
#define HID     2048
#define NEXP    8
#define PADMAX  9216                 // routed rows upper bound
#define MAXROWS (PADMAX + T_TOK)     // + shared-expert segment (13312)

// GEMM tiling (all half-precision element counts)
#define BM 128
#define BN 128
#define KC 32               // halves per k-slice
#define ASTR 40             // A row stride in halves (32 + 8 pad, conflict-free)
#define BSTR 40             // B row stride in halves ([n][k] layout)
#define STAGES 4
#define SA (BM * ASTR)      // halves per A stage (5120)
#define SB (BN * BSTR)      // halves per B stage (5120)

// ---------------- scratch (device globals: allocation-free) ----------------
__device__ int    g_counts[NEXP];
__device__ int    g_seg[NEXP + 2];
__device__ int    g_cursor[NEXP];
__device__ int    g_topk_idx[T_TOK * 2];
__device__ float  g_topk_gate[T_TOK * 2];
__device__ int    g_perm_token[MAXROWS];
__device__ int    g_inv[T_TOK * 2];
__device__ __half g_xh[(size_t)T_TOK * DM];           // fp16 X
__device__ __half g_w1t[(size_t)NEXP * HID * DM];     // [e][h][d]
__device__ __half g_w3t[(size_t)NEXP * HID * DM];     // [e][h][d]
__device__ __half g_w2t[(size_t)NEXP * DM * HID];     // [e][d][h]
__device__ __half g_sw1t[(size_t)HID * DM];
__device__ __half g_sw3t[(size_t)HID * DM];
__device__ __half g_sw2t[(size_t)DM * HID];
__device__ __half g_acth[(size_t)MAXROWS * HID];      // fp16 SwiGLU activations
__device__ float  g_y[(size_t)MAXROWS * DM];          // fp32 expert outputs

// ---------------- helpers ----------------
__device__ __forceinline__ void mma_f16(float* d, const unsigned* a, const unsigned* b) {
    asm volatile(
        "mma.sync.aligned.m16n8k16.row.col.f32.f16.f16.f32 "
        "{%0,%1,%2,%3}, {%4,%5,%6,%7}, {%8,%9}, {%0,%1,%2,%3};\n"
        : "+f"(d[0]), "+f"(d[1]), "+f"(d[2]), "+f"(d[3])
        : "r"(a[0]), "r"(a[1]), "r"(a[2]), "r"(a[3]), "r"(b[0]), "r"(b[1]));
}

__device__ __forceinline__ void cp_async16h(__half* smem_dst, const __half* gmem_src) {
    unsigned s = (unsigned)__cvta_generic_to_shared(smem_dst);
    asm volatile("cp.async.cg.shared.global [%0], [%1], 16;\n" :: "r"(s), "l"(gmem_src));
}
__device__ __forceinline__ void cp_commit() {
    asm volatile("cp.async.commit_group;\n");
}
template <int N>
__device__ __forceinline__ void cp_wait() {
    asm volatile("cp.async.wait_group %0;\n" :: "n"(N));
}

__device__ __forceinline__ float silu_f(float h) {
    return __fdividef(h, 1.0f + __expf(-h));
}

// ---------------- stage 0: reset ----------------
__global__ void reset_kernel() {
    int i = blockIdx.x * blockDim.x + threadIdx.x;
    if (i < NEXP) g_counts[i] = 0;
    for (int p = i; p < MAXROWS; p += gridDim.x * blockDim.x) g_perm_token[p] = 0;
}

// ---------------- convert X -> fp16 ----------------
__global__ void cvt_x_kernel(const float* __restrict__ X) {
    int i = blockIdx.x * blockDim.x + threadIdx.x;   // over float4s
    float4 v = reinterpret_cast<const float4*>(X)[i];
    __half2* dst = reinterpret_cast<__half2*>(g_xh);
    dst[2 * i]     = __floats2half2_rn(v.x, v.y);
    dst[2 * i + 1] = __floats2half2_rn(v.z, v.w);
}

// ---------------- convert + transpose weights: in[R][C] fp32 -> out[C][R] fp16 ----------------
__global__ __launch_bounds__(256) void transpose_cvt_kernel(
    const float* __restrict__ in, __half* __restrict__ out, int R, int C) {
    __shared__ __half tile[64][66];
    size_t moff = (size_t)blockIdx.z * R * C;
    in += moff; out += moff;
    int c0 = blockIdx.x * 64, r0 = blockIdx.y * 64;

    int fc = threadIdx.x & 15, row4 = threadIdx.x >> 4;
#pragma unroll
    for (int p = 0; p < 4; p++) {
        int r = row4 + p * 16;
        float4 v = *reinterpret_cast<const float4*>(in + (size_t)(r0 + r) * C + c0 + fc * 4);
        tile[fc * 4 + 0][r] = __float2half_rn(v.x);
        tile[fc * 4 + 1][r] = __float2half_rn(v.y);
        tile[fc * 4 + 2][r] = __float2half_rn(v.z);
        tile[fc * 4 + 3][r] = __float2half_rn(v.w);
    }
    __syncthreads();

    int oc = threadIdx.x >> 2, seg = threadIdx.x & 3;
    unsigned u[8];
#pragma unroll
    for (int j = 0; j < 8; j++) {
        __half2 hh = __halves2half2(tile[oc][seg * 16 + 2 * j], tile[oc][seg * 16 + 2 * j + 1]);
        u[j] = *reinterpret_cast<unsigned*>(&hh);
    }
    uint4* dst = reinterpret_cast<uint4*>(out + (size_t)(c0 + oc) * R + r0 + seg * 16);
    dst[0] = make_uint4(u[0], u[1], u[2], u[3]);
    dst[1] = make_uint4(u[4], u[5], u[6], u[7]);
}

// ---------------- stage 1: router (one warp per token) ----------------
__global__ __launch_bounds__(256) void router_kernel(const float* __restrict__ X,
                                                     const float* __restrict__ WR) {
    int warp = threadIdx.x >> 5, lane = threadIdx.x & 31;
    int t = blockIdx.x * 8 + warp;
    if (t >= T_TOK) return;

    float acc[8];
#pragma unroll
    for (int e = 0; e < 8; e++) acc[e] = 0.0f;

    const float* xr = X + (size_t)t * DM;
    for (int i = lane; i < DM; i += 32) {
        float xv = xr[i];
        const float4* w = reinterpret_cast<const float4*>(WR + (size_t)i * NEXP);
        float4 w0 = w[0], w1 = w[1];
        acc[0] += xv * w0.x; acc[1] += xv * w0.y; acc[2] += xv * w0.z; acc[3] += xv * w0.w;
        acc[4] += xv * w1.x; acc[5] += xv * w1.y; acc[6] += xv * w1.z; acc[7] += xv * w1.w;
    }
#pragma unroll
    for (int e = 0; e < 8; e++)
#pragma unroll
        for (int off = 16; off > 0; off >>= 1)
            acc[e] += __shfl_xor_sync(0xffffffffu, acc[e], off);

    if (lane == 0) {
        int i0 = 0; float v0 = acc[0];
#pragma unroll
        for (int e = 1; e < 8; e++) if (acc[e] > v0) { v0 = acc[e]; i0 = e; }
        int i1 = -1; float v1 = -3.4e38f;
#pragma unroll
        for (int e = 0; e < 8; e++) if (e != i0 && acc[e] > v1) { v1 = acc[e]; i1 = e; }
        float r  = expf(v1 - v0);
        float g0 = 1.0f / (1.0f + r);
        float g1 = r / (1.0f + r);
        g_topk_idx[t * 2]      = i0;
        g_topk_idx[t * 2 + 1]  = i1;
        g_topk_gate[t * 2]     = g0;
        g_topk_gate[t * 2 + 1] = g1;
        atomicAdd(&g_counts[i0], 1);
        atomicAdd(&g_counts[i1], 1);
    }
}

// ---------------- stage 2: segment scan ----------------
__global__ void scan_kernel() {
    if (threadIdx.x == 0 && blockIdx.x == 0) {
        int s = 0;
        for (int e = 0; e < NEXP; e++) {
            g_seg[e] = s;
            g_cursor[e] = s;
            s += (g_counts[e] + BM - 1) & ~(BM - 1);
        }
        g_seg[NEXP] = s;
        g_seg[NEXP + 1] = s + T_TOK;
    }
}

// ---------------- stage 3: build permutation ----------------
__global__ void fill_kernel() {
    int i = blockIdx.x * blockDim.x + threadIdx.x;
    if (i < T_TOK * 2) {
        int e = g_topk_idx[i];
        int p = atomicAdd(&g_cursor[e], 1);
        g_perm_token[p] = i >> 1;
        g_inv[i] = p;
    } else if (i < T_TOK * 3) {
        int t = i - T_TOK * 2;
        g_perm_token[g_seg[NEXP] + t] = t;
    }
}

// ---------------- stage 4: fused SwiGLU up-projection grouped GEMM (fp16) ----------------
__global__ __launch_bounds__(256) void gemm1_kernel(
    const __half* __restrict__ W1T, const __half* __restrict__ W3T,
    const __half* __restrict__ SW1T, const __half* __restrict__ SW3T) {
    extern __shared__ __half smh[];
    __half* As  = smh;                   // STAGES * SA
    __half* B1s = smh + STAGES * SA;
    __half* B3s = B1s + STAGES * SB;

    int base = blockIdx.y * BM;
    int total = g_seg[NEXP + 1];
    if (base >= total) return;
    int e = 0;
    while (g_seg[e + 1] <= base) e++;

    const __half* W1e = (e < NEXP) ? W1T + (size_t)e * HID * DM : SW1T;
    const __half* W3e = (e < NEXP) ? W3T + (size_t)e * HID * DM : SW3T;
    int nb = blockIdx.x * BN;

    int tid = threadIdx.x, lane = tid & 31, warp = tid >> 5;
    int wm = warp & 3, wn = warp >> 2;     // 4x2 warps, warp tile 32x64
    int g = lane >> 2, tig = lane & 3;

    // A: 128 rows x 4 chunks(16B) = 512, 2 per thread
    int ar[2], ach[2];
    const __half* aptr[2];
#pragma unroll
    for (int it = 0; it < 2; it++) {
        int pos = tid + 256 * it;
        int r = pos >> 2, ch = pos & 3;
        ar[it] = r; ach[it] = ch * 8;
        int gr = g_perm_token[base + r];
        aptr[it] = g_xh + (size_t)gr * DM + ch * 8;
    }
    // B: per matrix 128 rows x 4 chunks = 512, 2 per thread
    int brow[2];
    int bch = (tid & 3) * 8;
#pragma unroll
    for (int it = 0; it < 2; it++) brow[it] = (tid >> 2) + 64 * it;

    float acc1[2][8][4], acc3[2][8][4];
#pragma unroll
    for (int mt = 0; mt < 2; mt++)
#pragma unroll
        for (int nt = 0; nt < 8; nt++)
#pragma unroll
            for (int q = 0; q < 4; q++) { acc1[mt][nt][q] = 0.0f; acc3[mt][nt][q] = 0.0f; }

    const int iters = DM / KC;   // 32

    auto issue = [&](int k, int st) {
        int kb = k * KC;
#pragma unroll
        for (int it = 0; it < 2; it++)
            cp_async16h(&As[st * SA + ar[it] * ASTR + ach[it]], aptr[it] + kb);
#pragma unroll
        for (int it = 0; it < 2; it++) {
            int n = brow[it];
            cp_async16h(&B1s[st * SB + n * BSTR + bch], W1e + (size_t)(nb + n) * DM + kb + bch);
            cp_async16h(&B3s[st * SB + n * BSTR + bch], W3e + (size_t)(nb + n) * DM + kb + bch);
        }
        cp_commit();
    };

    issue(0, 0);
    issue(1, 1);
    issue(2, 2);

    int st = 0;
    for (int k = 0; k < iters; k++) {
        if (k + 2 < iters) cp_wait<2>();
        else if (k + 1 < iters) cp_wait<1>();
        else cp_wait<0>();
        __syncthreads();
        if (k + 3 < iters) issue(k + 3, (k + 3) & (STAGES - 1));

        const __half* Ast = As + st * SA;
        const __half* B1t = B1s + st * SB;
        const __half* B3t = B3s + st * SB;
#pragma unroll
        for (int ks = 0; ks < 2; ks++) {
            int k16 = ks * 16;
            unsigned a[2][4];
#pragma unroll
            for (int mt = 0; mt < 2; mt++) {
                int rr = wm * 32 + mt * 16;
                a[mt][0] = *reinterpret_cast<const unsigned*>(&Ast[(rr + g) * ASTR + k16 + 2 * tig]);
                a[mt][1] = *reinterpret_cast<const unsigned*>(&Ast[(rr + g + 8) * ASTR + k16 + 2 * tig]);
                a[mt][2] = *reinterpret_cast<const unsigned*>(&Ast[(rr + g) * ASTR + k16 + 2 * tig + 8]);
                a[mt][3] = *reinterpret_cast<const unsigned*>(&Ast[(rr + g + 8) * ASTR + k16 + 2 * tig + 8]);
            }
            unsigned b1[8][2], b3[8][2];
#pragma unroll
            for (int nt = 0; nt < 8; nt++) {
                int cc = wn * 64 + nt * 8 + g;
                b1[nt][0] = *reinterpret_cast<const unsigned*>(&B1t[cc * BSTR + k16 + 2 * tig]);
                b1[nt][1] = *reinterpret_cast<const unsigned*>(&B1t[cc * BSTR + k16 + 2 * tig + 8]);
                b3[nt][0] = *reinterpret_cast<const unsigned*>(&B3t[cc * BSTR + k16 + 2 * tig]);
                b3[nt][1] = *reinterpret_cast<const unsigned*>(&B3t[cc * BSTR + k16 + 2 * tig + 8]);
            }
#pragma unroll
            for (int mt = 0; mt < 2; mt++)
#pragma unroll
                for (int nt = 0; nt < 8; nt++) {
                    mma_f16(acc1[mt][nt], a[mt], b1[nt]);
                    mma_f16(acc3[mt][nt], a[mt], b3[nt]);
                }
        }
        st = (st + 1) & (STAGES - 1);
    }

    // epilogue: act = silu(h1) * h3, stored fp16
#pragma unroll
    for (int mt = 0; mt < 2; mt++) {
#pragma unroll
        for (int nt = 0; nt < 8; nt++) {
            int r0 = base + wm * 32 + mt * 16 + g;
            int c  = nb + wn * 64 + nt * 8 + tig * 2;
            __half2 h0 = __floats2half2_rn(silu_f(acc1[mt][nt][0]) * acc3[mt][nt][0],
                                           silu_f(acc1[mt][nt][1]) * acc3[mt][nt][1]);
            __half2 h1 = __floats2half2_rn(silu_f(acc1[mt][nt][2]) * acc3[mt][nt][2],
                                           silu_f(acc1[mt][nt][3]) * acc3[mt][nt][3]);
            *reinterpret_cast<__half2*>(g_acth + (size_t)r0 * HID + c)       = h0;
            *reinterpret_cast<__half2*>(g_acth + (size_t)(r0 + 8) * HID + c) = h1;
        }
    }
}

// ---------------- stage 5: down-projection grouped GEMM (fp16) ----------------
__global__ __launch_bounds__(256) void gemm2_kernel(
    const __half* __restrict__ W2T, const __half* __restrict__ SW2T) {
    extern __shared__ __half smh[];
    __half* As = smh;                 // STAGES * SA
    __half* Bs = smh + STAGES * SA;   // STAGES * SB

    int base = blockIdx.y * BM;
    int total = g_seg[NEXP + 1];
    if (base >= total) return;
    int e = 0;
    while (g_seg[e + 1] <= base) e++;

    const __half* W2e = (e < NEXP) ? W2T + (size_t)e * DM * HID : SW2T;
    int nb = blockIdx.x * BN;

    int tid = threadIdx.x, lane = tid & 31, warp = tid >> 5;
    int wm = warp & 3, wn = warp >> 2;
    int g = lane >> 2, tig = lane & 3;

    int ar[2], ach[2];
    const __half* aptr[2];
#pragma unroll
    for (int it = 0; it < 2; it++) {
        int pos = tid + 256 * it;
        int r = pos >> 2, ch = pos & 3;
        ar[it] = r; ach[it] = ch * 8;
        aptr[it] = g_acth + (size_t)(base + r) * HID + ch * 8;
    }
    int brow[2];
    int bch = (tid & 3) * 8;
#pragma unroll
    for (int it = 0; it < 2; it++) brow[it] = (tid >> 2) + 64 * it;

    float acc[2][8][4];
#pragma unroll
    for (int mt = 0; mt < 2; mt++)
#pragma unroll
        for (int nt = 0; nt < 8; nt++)
#pragma unroll
            for (int q = 0; q < 4; q++) acc[mt][nt][q] = 0.0f;

    const int iters = HID / KC;   // 64

    auto issue = [&](int k, int st) {
        int kb = k * KC;
#pragma unroll
        for (int it = 0; it < 2; it++)
            cp_async16h(&As[st * SA + ar[it] * ASTR + ach[it]], aptr[it] + kb);
#pragma unroll
        for (int it = 0; it < 2; it++) {
            int n = brow[it];
            cp_async16h(&Bs[st * SB + n * BSTR + bch], W2e + (size_t)(nb + n) * HID + kb + bch);
        }
        cp_commit();
    };

    issue(0, 0);
    issue(1, 1);
    issue(2, 2);

    int st = 0;
    for (int k = 0; k < iters; k++) {
        if (k + 2 < iters) cp_wait<2>();
        else if (k + 1 < iters) cp_wait<1>();
        else cp_wait<0>();
        __syncthreads();
        if (k + 3 < iters) issue(k + 3, (k + 3) & (STAGES - 1));

        const __half* Ast = As + st * SA;
        const __half* Bt  = Bs + st * SB;
#pragma unroll
        for (int ks = 0; ks < 2; ks++) {
            int k16 = ks * 16;
            unsigned a[2][4];
#pragma unroll
            for (int mt = 0; mt < 2; mt++) {
                int rr = wm * 32 + mt * 16;
                a[mt][0] = *reinterpret_cast<const unsigned*>(&Ast[(rr + g) * ASTR + k16 + 2 * tig]);
                a[mt][1] = *reinterpret_cast<const unsigned*>(&Ast[(rr + g + 8) * ASTR + k16 + 2 * tig]);
                a[mt][2] = *reinterpret_cast<const unsigned*>(&Ast[(rr + g) * ASTR + k16 + 2 * tig + 8]);
                a[mt][3] = *reinterpret_cast<const unsigned*>(&Ast[(rr + g + 8) * ASTR + k16 + 2 * tig + 8]);
            }
            unsigned b[8][2];
#pragma unroll
            for (int nt = 0; nt < 8; nt++) {
                int cc = wn * 64 + nt * 8 + g;
                b[nt][0] = *reinterpret_cast<const unsigned*>(&Bt[cc * BSTR + k16 + 2 * tig]);
                b[nt][1] = *reinterpret_cast<const unsigned*>(&Bt[cc * BSTR + k16 + 2 * tig + 8]);
            }
#pragma unroll
            for (int mt = 0; mt < 2; mt++)
#pragma unroll
                for (int nt = 0; nt < 8; nt++)
                    mma_f16(acc[mt][nt], a[mt], b[nt]);
        }
        st = (st + 1) & (STAGES - 1);
    }

#pragma unroll
    for (int mt = 0; mt < 2; mt++) {
#pragma unroll
        for (int nt = 0; nt < 8; nt++) {
            int r0 = base + wm * 32 + mt * 16 + g;
            int c  = nb + wn * 64 + nt * 8 + tig * 2;
            float2 o0, o1;
            o0.x = acc[mt][nt][0]; o0.y = acc[mt][nt][1];
            o1.x = acc[mt][nt][2]; o1.y = acc[mt][nt][3];
            *reinterpret_cast<float2*>(g_y + (size_t)r0 * DM + c)       = o0;
            *reinterpret_cast<float2*>(g_y + (size_t)(r0 + 8) * DM + c) = o1;
        }
    }
}

// ---------------- stage 6: combine shared + gated routed ----------------
__global__ void combine_kernel(float* __restrict__ OUT) {
    int i = blockIdx.x * blockDim.x + threadIdx.x;
    if (i >= T_TOK * DM) return;
    int t = i >> 10;
    int d = i & 1023;
    int s8 = g_seg[NEXP];
    int p0 = g_inv[t * 2];
    int p1 = g_inv[t * 2 + 1];
    float v = g_y[(size_t)(s8 + t) * DM + d];
    v += g_topk_gate[t * 2]     * g_y[(size_t)p0 * DM + d];
    v += g_topk_gate[t * 2 + 1] * g_y[(size_t)p1 * DM + d];
    OUT[i] = v;
}

// ---------------- launch ----------------
#define G1_SMEM ((STAGES * SA + 2 * STAGES * SB) * 2)   // 122880 bytes
#define G2_SMEM ((STAGES * SA + STAGES * SB) * 2)       // 81920 bytes

extern "C" void kernel_launch(void* const* d_in, const int* in_sizes, int n_in,
                              void* d_out, int out_size) {
    (void)in_sizes; (void)n_in; (void)out_size;
    const float* x   = (const float*)d_in[0];
    const float* wr  = (const float*)d_in[1];
    const float* w1  = (const float*)d_in[2];
    const float* w3  = (const float*)d_in[3];
    const float* w2  = (const float*)d_in[4];
    const float* sw1 = (const float*)d_in[5];
    const float* sw3 = (const float*)d_in[6];
    const float* sw2 = (const float*)d_in[7];
    float* out = (float*)d_out;

    __half *w1t, *w3t, *w2t, *sw1t, *sw3t, *sw2t;
    cudaGetSymbolAddress((void**)&w1t,  g_w1t);
    cudaGetSymbolAddress((void**)&w3t,  g_w3t);
    cudaGetSymbolAddress((void**)&w2t,  g_w2t);
    cudaGetSymbolAddress((void**)&sw1t, g_sw1t);
    cudaGetSymbolAddress((void**)&sw3t, g_sw3t);
    cudaGetSymbolAddress((void**)&sw2t, g_sw2t);

    cudaFuncSetAttribute(gemm1_kernel, cudaFuncAttributeMaxDynamicSharedMemorySize, G1_SMEM);
    cudaFuncSetAttribute(gemm2_kernel, cudaFuncAttributeMaxDynamicSharedMemorySize, G2_SMEM);

    reset_kernel<<<52, 256>>>();
    router_kernel<<<512, 256>>>(x, wr);
    scan_kernel<<<1, 32>>>();
    fill_kernel<<<48, 256>>>();

    // precision conversion + weight transposition (fp32 -> fp16, [k][n] -> [n][k])
    cvt_x_kernel<<<(T_TOK * DM / 4) / 256, 256>>>(x);
    transpose_cvt_kernel<<<dim3(HID / 64, DM / 64, NEXP), 256>>>(w1, w1t, DM, HID);
    transpose_cvt_kernel<<<dim3(HID / 64, DM / 64, NEXP), 256>>>(w3, w3t, DM, HID);
    transpose_cvt_kernel<<<dim3(DM / 64, HID / 64, NEXP), 256>>>(w2, w2t, HID, DM);
    transpose_cvt_kernel<<<dim3(HID / 64, DM / 64, 1), 256>>>(sw1, sw1t, DM, HID);
    transpose_cvt_kernel<<<dim3(HID / 64, DM / 64, 1), 256>>>(sw3, sw3t, DM, HID);
    transpose_cvt_kernel<<<dim3(DM / 64, HID / 64, 1), 256>>>(sw2, sw2t, HID, DM);

    // all experts (8 routed segments + shared segment) in two grouped GEMMs
    gemm1_kernel<<<dim3(HID / BN, MAXROWS / BM), 256, G1_SMEM>>>(w1t, w3t, sw1t, sw3t);
    gemm2_kernel<<<dim3(DM / BN, MAXROWS / BM), 256, G2_SMEM>>>(w2t, sw2t);

    // final combine writes d_out
    combine_kernel<<<(T_TOK * DM) / 256, 256>>>(out);
}

// round 10
// speedup vs baseline: 2.5443x; 1.1000x over previous
#include <cuda_runtime.h>
#include <cuda_fp16.h>
#include <cstdint>

// Problem constants
#define T_TOK   4096
#define DM      1024
#define HID     2048
#define NEXP    8
#define PADMAX  9216
#define MAXROWS (PADMAX + T_TOK)     // 13312

// GEMM tiling (half-precision element counts)
#define BM 128
#define BN 128
#define KC 64               // halves per k-slice
#define ASTR 72             // row stride in halves (64 + 8 pad; 144B rows, conflict-free)
#define ROWB (ASTR * 2)     // 144 bytes
#define STAGES 3
#define SA (BM * ASTR)      // halves per tile (9216)

// ---------------- scratch (device globals: allocation-free) ----------------
__device__ int    g_counts[NEXP];
__device__ int    g_seg[NEXP + 2];
__device__ int    g_cursor[NEXP];
__device__ int    g_topk_idx[T_TOK * 2];
__device__ float  g_topk_gate[T_TOK * 2];
__device__ int    g_perm_token[MAXROWS];
__device__ int    g_inv[T_TOK * 2];
__device__ __half g_xh[(size_t)T_TOK * DM];           // fp16 X
__device__ __half g_w1t[(size_t)NEXP * HID * DM];     // [e][h][d]
__device__ __half g_w3t[(size_t)NEXP * HID * DM];
__device__ __half g_w2t[(size_t)NEXP * DM * HID];     // [e][d][h]
__device__ __half g_sw1t[(size_t)HID * DM];
__device__ __half g_sw3t[(size_t)HID * DM];
__device__ __half g_sw2t[(size_t)DM * HID];
__device__ __half g_acth[(size_t)MAXROWS * HID];      // fp16 SwiGLU activations
__device__ float  g_y[(size_t)MAXROWS * DM];          // fp32 expert outputs

// ---------------- helpers ----------------
__device__ __forceinline__ uint32_t smem_u32(const void* p) {
    return (uint32_t)__cvta_generic_to_shared(p);
}
__device__ __forceinline__ void mma_f16(float* d, const unsigned* a, const unsigned* b) {
    asm volatile(
        "mma.sync.aligned.m16n8k16.row.col.f32.f16.f16.f32 "
        "{%0,%1,%2,%3}, {%4,%5,%6,%7}, {%8,%9}, {%0,%1,%2,%3};\n"
        : "+f"(d[0]), "+f"(d[1]), "+f"(d[2]), "+f"(d[3])
        : "r"(a[0]), "r"(a[1]), "r"(a[2]), "r"(a[3]), "r"(b[0]), "r"(b[1]));
}
__device__ __forceinline__ void ldsm_x4(unsigned* r, uint32_t addr) {
    asm volatile("ldmatrix.sync.aligned.m8n8.x4.shared.b16 {%0,%1,%2,%3}, [%4];"
                 : "=r"(r[0]), "=r"(r[1]), "=r"(r[2]), "=r"(r[3]) : "r"(addr));
}
__device__ __forceinline__ void ldsm_x2(unsigned* r, uint32_t addr) {
    asm volatile("ldmatrix.sync.aligned.m8n8.x2.shared.b16 {%0,%1}, [%2];"
                 : "=r"(r[0]), "=r"(r[1]) : "r"(addr));
}
__device__ __forceinline__ void cp16(uint32_t dst, const __half* src) {
    asm volatile("cp.async.cg.shared.global [%0], [%1], 16;\n" :: "r"(dst), "l"(src));
}
__device__ __forceinline__ void cp_commit() { asm volatile("cp.async.commit_group;\n"); }
template <int N> __device__ __forceinline__ void cp_wait() {
    asm volatile("cp.async.wait_group %0;\n" :: "n"(N));
}
__device__ __forceinline__ float silu_f(float h) {
    return __fdividef(h, 1.0f + __expf(-h));
}

// ---------------- stage 0: reset ----------------
__global__ void reset_kernel() {
    int i = blockIdx.x * blockDim.x + threadIdx.x;
    if (i < NEXP) g_counts[i] = 0;
    for (int p = i; p < MAXROWS; p += gridDim.x * blockDim.x) g_perm_token[p] = 0;
}

// ---------------- convert X -> fp16 ----------------
__global__ void cvt_x_kernel(const float* __restrict__ X) {
    int i = blockIdx.x * blockDim.x + threadIdx.x;
    float4 v = reinterpret_cast<const float4*>(X)[i];
    __half2* dst = reinterpret_cast<__half2*>(g_xh);
    dst[2 * i]     = __floats2half2_rn(v.x, v.y);
    dst[2 * i + 1] = __floats2half2_rn(v.z, v.w);
}

// ---------------- convert + transpose weights: in[R][C] fp32 -> out[C][R] fp16 ----------------
__global__ __launch_bounds__(256) void transpose_cvt_kernel(
    const float* __restrict__ in, __half* __restrict__ out, int R, int C) {
    __shared__ __half tile[64][66];
    size_t moff = (size_t)blockIdx.z * R * C;
    in += moff; out += moff;
    int c0 = blockIdx.x * 64, r0 = blockIdx.y * 64;

    int fc = threadIdx.x & 15, row4 = threadIdx.x >> 4;
#pragma unroll
    for (int p = 0; p < 4; p++) {
        int r = row4 + p * 16;
        float4 v = *reinterpret_cast<const float4*>(in + (size_t)(r0 + r) * C + c0 + fc * 4);
        tile[fc * 4 + 0][r] = __float2half_rn(v.x);
        tile[fc * 4 + 1][r] = __float2half_rn(v.y);
        tile[fc * 4 + 2][r] = __float2half_rn(v.z);
        tile[fc * 4 + 3][r] = __float2half_rn(v.w);
    }
    __syncthreads();

    int oc = threadIdx.x >> 2, seg = threadIdx.x & 3;
    unsigned u[8];
#pragma unroll
    for (int j = 0; j < 8; j++) {
        __half2 hh = __halves2half2(tile[oc][seg * 16 + 2 * j], tile[oc][seg * 16 + 2 * j + 1]);
        u[j] = *reinterpret_cast<unsigned*>(&hh);
    }
    uint4* dst = reinterpret_cast<uint4*>(out + (size_t)(c0 + oc) * R + r0 + seg * 16);
    dst[0] = make_uint4(u[0], u[1], u[2], u[3]);
    dst[1] = make_uint4(u[4], u[5], u[6], u[7]);
}

// ---------------- stage 1: router ----------------
__global__ __launch_bounds__(256) void router_kernel(const float* __restrict__ X,
                                                     const float* __restrict__ WR) {
    int warp = threadIdx.x >> 5, lane = threadIdx.x & 31;
    int t = blockIdx.x * 8 + warp;
    if (t >= T_TOK) return;

    float acc[8];
#pragma unroll
    for (int e = 0; e < 8; e++) acc[e] = 0.0f;

    const float* xr = X + (size_t)t * DM;
    for (int i = lane; i < DM; i += 32) {
        float xv = xr[i];
        const float4* w = reinterpret_cast<const float4*>(WR + (size_t)i * NEXP);
        float4 w0 = w[0], w1 = w[1];
        acc[0] += xv * w0.x; acc[1] += xv * w0.y; acc[2] += xv * w0.z; acc[3] += xv * w0.w;
        acc[4] += xv * w1.x; acc[5] += xv * w1.y; acc[6] += xv * w1.z; acc[7] += xv * w1.w;
    }
#pragma unroll
    for (int e = 0; e < 8; e++)
#pragma unroll
        for (int off = 16; off > 0; off >>= 1)
            acc[e] += __shfl_xor_sync(0xffffffffu, acc[e], off);

    if (lane == 0) {
        int i0 = 0; float v0 = acc[0];
#pragma unroll
        for (int e = 1; e < 8; e++) if (acc[e] > v0) { v0 = acc[e]; i0 = e; }
        int i1 = -1; float v1 = -3.4e38f;
#pragma unroll
        for (int e = 0; e < 8; e++) if (e != i0 && acc[e] > v1) { v1 = acc[e]; i1 = e; }
        float r  = expf(v1 - v0);
        float g0 = 1.0f / (1.0f + r);
        float g1 = r / (1.0f + r);
        g_topk_idx[t * 2]      = i0;
        g_topk_idx[t * 2 + 1]  = i1;
        g_topk_gate[t * 2]     = g0;
        g_topk_gate[t * 2 + 1] = g1;
        atomicAdd(&g_counts[i0], 1);
        atomicAdd(&g_counts[i1], 1);
    }
}

// ---------------- stage 2: segment scan ----------------
__global__ void scan_kernel() {
    if (threadIdx.x == 0 && blockIdx.x == 0) {
        int s = 0;
        for (int e = 0; e < NEXP; e++) {
            g_seg[e] = s;
            g_cursor[e] = s;
            s += (g_counts[e] + BM - 1) & ~(BM - 1);
        }
        g_seg[NEXP] = s;
        g_seg[NEXP + 1] = s + T_TOK;
    }
}

// ---------------- stage 3: build permutation ----------------
__global__ void fill_kernel() {
    int i = blockIdx.x * blockDim.x + threadIdx.x;
    if (i < T_TOK * 2) {
        int e = g_topk_idx[i];
        int p = atomicAdd(&g_cursor[e], 1);
        g_perm_token[p] = i >> 1;
        g_inv[i] = p;
    } else if (i < T_TOK * 3) {
        int t = i - T_TOK * 2;
        g_perm_token[g_seg[NEXP] + t] = t;
    }
}

// ======================================================================
// fp16 mma.sync grouped GEMMs (KC=64, ldmatrix fragments, 3-stage cp.async)
// ======================================================================

extern __shared__ __align__(16) __half smh[];

// stage 4: SwiGLU up-projection: ACT = silu(X W1) * (X W3), fp16 out
__global__ __launch_bounds__(256, 1) void gemm1_kernel(
    const __half* __restrict__ W1T, const __half* __restrict__ W3T,
    const __half* __restrict__ SW1T, const __half* __restrict__ SW3T) {
    int base = blockIdx.y * BM;
    if (base >= g_seg[NEXP + 1]) return;
    int e = 0;
    while (g_seg[e + 1] <= base) e++;
    const __half* W1e = (e < NEXP) ? W1T + (size_t)e * HID * DM : SW1T;
    const __half* W3e = (e < NEXP) ? W3T + (size_t)e * HID * DM : SW3T;
    int nb = blockIdx.x * BN;

    int tid = threadIdx.x, lane = tid & 31, warp = tid >> 5;
    int wm = warp & 3, wn = warp >> 2;     // 4x2 warps, warp tile 32(m)x64(n)

    uint32_t sbase = smem_u32(smh);

    // producer mapping: per tile 128 rows x 8 chunks(16B); 4 rows per thread
    int ch = tid & 7;
    int rows[4];
    const __half* asrc[4];
    uint32_t dstoff[4];
#pragma unroll
    for (int i = 0; i < 4; i++) {
        int r = (tid >> 3) + 32 * i;
        rows[i] = r;
        asrc[i] = g_xh + (size_t)g_perm_token[base + r] * DM + ch * 8;
        dstoff[i] = (uint32_t)(r * ROWB + ch * 16);
    }

    // ldmatrix per-thread byte offsets within a tile
    uint32_t aoff[2];
#pragma unroll
    for (int mt = 0; mt < 2; mt++)
        aoff[mt] = (uint32_t)((wm * 32 + mt * 16 + (lane & 15)) * ROWB + (lane >> 4) * 16);
    uint32_t boff[8];
#pragma unroll
    for (int nt = 0; nt < 8; nt++)
        boff[nt] = (uint32_t)((wn * 64 + nt * 8 + (lane & 7)) * ROWB + ((lane >> 3) & 1) * 16);

    float acc1[2][8][4], acc3[2][8][4];
#pragma unroll
    for (int mt = 0; mt < 2; mt++)
#pragma unroll
        for (int nt = 0; nt < 8; nt++)
#pragma unroll
            for (int q = 0; q < 4; q++) { acc1[mt][nt][q] = 0.0f; acc3[mt][nt][q] = 0.0f; }

    const int nsl = DM / KC;   // 16

    auto issue = [&](int s) {
        uint32_t tb = sbase + (uint32_t)((s % STAGES) * 3 * SA * 2);
        int kb = s * KC;
#pragma unroll
        for (int i = 0; i < 4; i++) {
            cp16(tb + dstoff[i], asrc[i] + kb);
            cp16(tb + SA * 2 + dstoff[i], W1e + (size_t)(nb + rows[i]) * DM + kb + ch * 8);
            cp16(tb + 2 * SA * 2 + dstoff[i], W3e + (size_t)(nb + rows[i]) * DM + kb + ch * 8);
        }
        cp_commit();
    };

    issue(0);
    issue(1);

    for (int s = 0; s < nsl; s++) {
        if (s + 1 < nsl) cp_wait<1>(); else cp_wait<0>();
        __syncthreads();
        if (s + 2 < nsl) issue(s + 2);

        uint32_t tb = sbase + (uint32_t)((s % STAGES) * 3 * SA * 2);
        uint32_t aT = tb, b1T = tb + SA * 2, b3T = tb + 2 * SA * 2;
#pragma unroll
        for (int ks = 0; ks < 4; ks++) {
            uint32_t ko = ks * 32;   // 16 halves = 32 bytes
            unsigned a[2][4];
#pragma unroll
            for (int mt = 0; mt < 2; mt++) ldsm_x4(a[mt], aT + aoff[mt] + ko);
            unsigned b1[8][2], b3[8][2];
#pragma unroll
            for (int nt = 0; nt < 8; nt++) {
                ldsm_x2(b1[nt], b1T + boff[nt] + ko);
                ldsm_x2(b3[nt], b3T + boff[nt] + ko);
            }
#pragma unroll
            for (int mt = 0; mt < 2; mt++)
#pragma unroll
                for (int nt = 0; nt < 8; nt++) {
                    mma_f16(acc1[mt][nt], a[mt], b1[nt]);
                    mma_f16(acc3[mt][nt], a[mt], b3[nt]);
                }
        }
    }

    // epilogue: act = silu(h1) * h3, fp16
    int g = lane >> 2, tig = lane & 3;
#pragma unroll
    for (int mt = 0; mt < 2; mt++) {
#pragma unroll
        for (int nt = 0; nt < 8; nt++) {
            int r0 = base + wm * 32 + mt * 16 + g;
            int c  = nb + wn * 64 + nt * 8 + tig * 2;
            __half2 h0 = __floats2half2_rn(silu_f(acc1[mt][nt][0]) * acc3[mt][nt][0],
                                           silu_f(acc1[mt][nt][1]) * acc3[mt][nt][1]);
            __half2 h1 = __floats2half2_rn(silu_f(acc1[mt][nt][2]) * acc3[mt][nt][2],
                                           silu_f(acc1[mt][nt][3]) * acc3[mt][nt][3]);
            *reinterpret_cast<__half2*>(g_acth + (size_t)r0 * HID + c)       = h0;
            *reinterpret_cast<__half2*>(g_acth + (size_t)(r0 + 8) * HID + c) = h1;
        }
    }
}

// stage 5: down-projection: Y = ACT @ W2, fp32 out
__global__ __launch_bounds__(256, 1) void gemm2_kernel(
    const __half* __restrict__ W2T, const __half* __restrict__ SW2T) {
    int base = blockIdx.y * BM;
    if (base >= g_seg[NEXP + 1]) return;
    int e = 0;
    while (g_seg[e + 1] <= base) e++;
    const __half* W2e = (e < NEXP) ? W2T + (size_t)e * DM * HID : SW2T;
    int nb = blockIdx.x * BN;

    int tid = threadIdx.x, lane = tid & 31, warp = tid >> 5;
    int wm = warp & 3, wn = warp >> 2;

    uint32_t sbase = smem_u32(smh);

    int ch = tid & 7;
    int rows[4];
    uint32_t dstoff[4];
#pragma unroll
    for (int i = 0; i < 4; i++) {
        int r = (tid >> 3) + 32 * i;
        rows[i] = r;
        dstoff[i] = (uint32_t)(r * ROWB + ch * 16);
    }

    uint32_t aoff[2];
#pragma unroll
    for (int mt = 0; mt < 2; mt++)
        aoff[mt] = (uint32_t)((wm * 32 + mt * 16 + (lane & 15)) * ROWB + (lane >> 4) * 16);
    uint32_t boff[8];
#pragma unroll
    for (int nt = 0; nt < 8; nt++)
        boff[nt] = (uint32_t)((wn * 64 + nt * 8 + (lane & 7)) * ROWB + ((lane >> 3) & 1) * 16);

    float acc[2][8][4];
#pragma unroll
    for (int mt = 0; mt < 2; mt++)
#pragma unroll
        for (int nt = 0; nt < 8; nt++)
#pragma unroll
            for (int q = 0; q < 4; q++) acc[mt][nt][q] = 0.0f;

    const int nsl = HID / KC;   // 32

    auto issue = [&](int s) {
        uint32_t tb = sbase + (uint32_t)((s % STAGES) * 2 * SA * 2);
        int kb = s * KC;
#pragma unroll
        for (int i = 0; i < 4; i++) {
            cp16(tb + dstoff[i], g_acth + (size_t)(base + rows[i]) * HID + kb + ch * 8);
            cp16(tb + SA * 2 + dstoff[i], W2e + (size_t)(nb + rows[i]) * HID + kb + ch * 8);
        }
        cp_commit();
    };

    issue(0);
    issue(1);

    for (int s = 0; s < nsl; s++) {
        if (s + 1 < nsl) cp_wait<1>(); else cp_wait<0>();
        __syncthreads();
        if (s + 2 < nsl) issue(s + 2);

        uint32_t tb = sbase + (uint32_t)((s % STAGES) * 2 * SA * 2);
        uint32_t aT = tb, bT = tb + SA * 2;
#pragma unroll
        for (int ks = 0; ks < 4; ks++) {
            uint32_t ko = ks * 32;
            unsigned a[2][4];
#pragma unroll
            for (int mt = 0; mt < 2; mt++) ldsm_x4(a[mt], aT + aoff[mt] + ko);
            unsigned b[8][2];
#pragma unroll
            for (int nt = 0; nt < 8; nt++) ldsm_x2(b[nt], bT + boff[nt] + ko);
#pragma unroll
            for (int mt = 0; mt < 2; mt++)
#pragma unroll
                for (int nt = 0; nt < 8; nt++)
                    mma_f16(acc[mt][nt], a[mt], b[nt]);
        }
    }

    int g = lane >> 2, tig = lane & 3;
#pragma unroll
    for (int mt = 0; mt < 2; mt++) {
#pragma unroll
        for (int nt = 0; nt < 8; nt++) {
            int r0 = base + wm * 32 + mt * 16 + g;
            int c  = nb + wn * 64 + nt * 8 + tig * 2;
            float2 o0, o1;
            o0.x = acc[mt][nt][0]; o0.y = acc[mt][nt][1];
            o1.x = acc[mt][nt][2]; o1.y = acc[mt][nt][3];
            *reinterpret_cast<float2*>(g_y + (size_t)r0 * DM + c)       = o0;
            *reinterpret_cast<float2*>(g_y + (size_t)(r0 + 8) * DM + c) = o1;
        }
    }
}

// ---------------- stage 6: combine shared + gated routed ----------------
__global__ void combine_kernel(float* __restrict__ OUT) {
    int i = blockIdx.x * blockDim.x + threadIdx.x;
    if (i >= T_TOK * DM) return;
    int t = i >> 10;
    int d = i & 1023;
    int s8 = g_seg[NEXP];
    int p0 = g_inv[t * 2];
    int p1 = g_inv[t * 2 + 1];
    float v = g_y[(size_t)(s8 + t) * DM + d];
    v += g_topk_gate[t * 2]     * g_y[(size_t)p0 * DM + d];
    v += g_topk_gate[t * 2 + 1] * g_y[(size_t)p1 * DM + d];
    OUT[i] = v;
}

// ---------------- launch ----------------
#define G1_SMEM (STAGES * 3 * SA * 2)   // 165888 bytes
#define G2_SMEM (STAGES * 2 * SA * 2)   // 110592 bytes

extern "C" void kernel_launch(void* const* d_in, const int* in_sizes, int n_in,
                              void* d_out, int out_size) {
    (void)in_sizes; (void)n_in; (void)out_size;
    const float* x   = (const float*)d_in[0];
    const float* wr  = (const float*)d_in[1];
    const float* w1  = (const float*)d_in[2];
    const float* w3  = (const float*)d_in[3];
    const float* w2  = (const float*)d_in[4];
    const float* sw1 = (const float*)d_in[5];
    const float* sw3 = (const float*)d_in[6];
    const float* sw2 = (const float*)d_in[7];
    float* out = (float*)d_out;

    __half *w1t, *w3t, *w2t, *sw1t, *sw3t, *sw2t;
    cudaGetSymbolAddress((void**)&w1t,  g_w1t);
    cudaGetSymbolAddress((void**)&w3t,  g_w3t);
    cudaGetSymbolAddress((void**)&w2t,  g_w2t);
    cudaGetSymbolAddress((void**)&sw1t, g_sw1t);
    cudaGetSymbolAddress((void**)&sw3t, g_sw3t);
    cudaGetSymbolAddress((void**)&sw2t, g_sw2t);

    cudaFuncSetAttribute(gemm1_kernel, cudaFuncAttributeMaxDynamicSharedMemorySize, G1_SMEM);
    cudaFuncSetAttribute(gemm2_kernel, cudaFuncAttributeMaxDynamicSharedMemorySize, G2_SMEM);

    reset_kernel<<<52, 256>>>();
    router_kernel<<<512, 256>>>(x, wr);
    scan_kernel<<<1, 32>>>();
    fill_kernel<<<48, 256>>>();

    cvt_x_kernel<<<(T_TOK * DM / 4) / 256, 256>>>(x);
    transpose_cvt_kernel<<<dim3(HID / 64, DM / 64, NEXP), 256>>>(w1, w1t, DM, HID);
    transpose_cvt_kernel<<<dim3(HID / 64, DM / 64, NEXP), 256>>>(w3, w3t, DM, HID);
    transpose_cvt_kernel<<<dim3(DM / 64, HID / 64, NEXP), 256>>>(w2, w2t, HID, DM);
    transpose_cvt_kernel<<<dim3(HID / 64, DM / 64, 1), 256>>>(sw1, sw1t, DM, HID);
    transpose_cvt_kernel<<<dim3(HID / 64, DM / 64, 1), 256>>>(sw3, sw3t, DM, HID);
    transpose_cvt_kernel<<<dim3(DM / 64, HID / 64, 1), 256>>>(sw2, sw2t, HID, DM);

    gemm1_kernel<<<dim3(HID / BN, MAXROWS / BM), 256, G1_SMEM>>>(w1t, w3t, sw1t, sw3t);
    gemm2_kernel<<<dim3(DM / BN, MAXROWS / BM), 256, G2_SMEM>>>(w2t, sw2t);

    combine_kernel<<<(T_TOK * DM) / 256, 256>>>(out);
}

// round 11
// speedup vs baseline: 2.6240x; 1.0313x over previous
#include <cuda_runtime.h>
#include <cuda_fp16.h>
#include <cstdint>

// Problem constants
#define T_TOK   4096
#define DM      1024
#define HID     2048
#define NEXP    8
#define PADMAX  9216
#define MAXROWS (PADMAX + T_TOK)     // 13312

// GEMM tiling (half-precision element counts)
#define BM 128
#define BN 128
#define KC 64               // halves per k-slice
#define ASTR 72             // row stride in halves (64 + 8 pad; 144B rows, conflict-free)
#define ROWB (ASTR * 2)     // 144 bytes
#define STAGES 3
#define SA (BM * ASTR)      // halves per tile (9216)

// ---------------- scratch (device globals: allocation-free) ----------------
__device__ int    g_counts[NEXP];
__device__ int    g_seg[NEXP + 2];
__device__ int    g_cursor[NEXP];
__device__ int    g_topk_idx[T_TOK * 2];
__device__ float  g_topk_gate[T_TOK * 2];
__device__ int    g_perm_token[MAXROWS];
__device__ int    g_inv[T_TOK * 2];
__device__ __half g_xh[(size_t)T_TOK * DM];           // fp16 X
__device__ __half g_w1t[(size_t)NEXP * HID * DM];     // [e][h][d]
__device__ __half g_w3t[(size_t)NEXP * HID * DM];
__device__ __half g_w2t[(size_t)NEXP * DM * HID];     // [e][d][h]
__device__ __half g_sw1t[(size_t)HID * DM];
__device__ __half g_sw3t[(size_t)HID * DM];
__device__ __half g_sw2t[(size_t)DM * HID];
__device__ __half g_acth[(size_t)MAXROWS * HID];      // fp16 SwiGLU activations
__device__ float  g_y[(size_t)MAXROWS * DM];          // fp32 expert outputs

// ---------------- helpers ----------------
__device__ __forceinline__ uint32_t smem_u32(const void* p) {
    return (uint32_t)__cvta_generic_to_shared(p);
}
__device__ __forceinline__ void mma_f16(float* d, const unsigned* a, const unsigned* b) {
    asm volatile(
        "mma.sync.aligned.m16n8k16.row.col.f32.f16.f16.f32 "
        "{%0,%1,%2,%3}, {%4,%5,%6,%7}, {%8,%9}, {%0,%1,%2,%3};\n"
        : "+f"(d[0]), "+f"(d[1]), "+f"(d[2]), "+f"(d[3])
        : "r"(a[0]), "r"(a[1]), "r"(a[2]), "r"(a[3]), "r"(b[0]), "r"(b[1]));
}
__device__ __forceinline__ void ldsm_x4(unsigned* r, uint32_t addr) {
    asm volatile("ldmatrix.sync.aligned.m8n8.x4.shared.b16 {%0,%1,%2,%3}, [%4];"
                 : "=r"(r[0]), "=r"(r[1]), "=r"(r[2]), "=r"(r[3]) : "r"(addr));
}
__device__ __forceinline__ void cp16(uint32_t dst, const __half* src) {
    asm volatile("cp.async.cg.shared.global [%0], [%1], 16;\n" :: "r"(dst), "l"(src));
}
__device__ __forceinline__ void cp_commit() { asm volatile("cp.async.commit_group;\n"); }
template <int N> __device__ __forceinline__ void cp_wait() {
    asm volatile("cp.async.wait_group %0;\n" :: "n"(N));
}
__device__ __forceinline__ float silu_f(float h) {
    return __fdividef(h, 1.0f + __expf(-h));
}

// ---------------- stage 0: reset ----------------
__global__ void reset_kernel() {
    int i = blockIdx.x * blockDim.x + threadIdx.x;
    if (i < NEXP) g_counts[i] = 0;
    for (int p = i; p < MAXROWS; p += gridDim.x * blockDim.x) g_perm_token[p] = 0;
}

// ---------------- convert X -> fp16 ----------------
__global__ void cvt_x_kernel(const float* __restrict__ X) {
    int i = blockIdx.x * blockDim.x + threadIdx.x;
    float4 v = reinterpret_cast<const float4*>(X)[i];
    __half2* dst = reinterpret_cast<__half2*>(g_xh);
    dst[2 * i]     = __floats2half2_rn(v.x, v.y);
    dst[2 * i + 1] = __floats2half2_rn(v.z, v.w);
}

// ---------------- convert + transpose weights: in[R][C] fp32 -> out[C][R] fp16 ----------------
__global__ __launch_bounds__(256) void transpose_cvt_kernel(
    const float* __restrict__ in, __half* __restrict__ out, int R, int C) {
    __shared__ __half tile[64][66];
    size_t moff = (size_t)blockIdx.z * R * C;
    in += moff; out += moff;
    int c0 = blockIdx.x * 64, r0 = blockIdx.y * 64;

    int fc = threadIdx.x & 15, row4 = threadIdx.x >> 4;
#pragma unroll
    for (int p = 0; p < 4; p++) {
        int r = row4 + p * 16;
        float4 v = *reinterpret_cast<const float4*>(in + (size_t)(r0 + r) * C + c0 + fc * 4);
        tile[fc * 4 + 0][r] = __float2half_rn(v.x);
        tile[fc * 4 + 1][r] = __float2half_rn(v.y);
        tile[fc * 4 + 2][r] = __float2half_rn(v.z);
        tile[fc * 4 + 3][r] = __float2half_rn(v.w);
    }
    __syncthreads();

    int oc = threadIdx.x >> 2, seg = threadIdx.x & 3;
    unsigned u[8];
#pragma unroll
    for (int j = 0; j < 8; j++) {
        __half2 hh = __halves2half2(tile[oc][seg * 16 + 2 * j], tile[oc][seg * 16 + 2 * j + 1]);
        u[j] = *reinterpret_cast<unsigned*>(&hh);
    }
    uint4* dst = reinterpret_cast<uint4*>(out + (size_t)(c0 + oc) * R + r0 + seg * 16);
    dst[0] = make_uint4(u[0], u[1], u[2], u[3]);
    dst[1] = make_uint4(u[4], u[5], u[6], u[7]);
}

// ---------------- stage 1: router ----------------
__global__ __launch_bounds__(256) void router_kernel(const float* __restrict__ X,
                                                     const float* __restrict__ WR) {
    int warp = threadIdx.x >> 5, lane = threadIdx.x & 31;
    int t = blockIdx.x * 8 + warp;
    if (t >= T_TOK) return;

    float acc[8];
#pragma unroll
    for (int e = 0; e < 8; e++) acc[e] = 0.0f;

    const float* xr = X + (size_t)t * DM;
    for (int i = lane; i < DM; i += 32) {
        float xv = xr[i];
        const float4* w = reinterpret_cast<const float4*>(WR + (size_t)i * NEXP);
        float4 w0 = w[0], w1 = w[1];
        acc[0] += xv * w0.x; acc[1] += xv * w0.y; acc[2] += xv * w0.z; acc[3] += xv * w0.w;
        acc[4] += xv * w1.x; acc[5] += xv * w1.y; acc[6] += xv * w1.z; acc[7] += xv * w1.w;
    }
#pragma unroll
    for (int e = 0; e < 8; e++)
#pragma unroll
        for (int off = 16; off > 0; off >>= 1)
            acc[e] += __shfl_xor_sync(0xffffffffu, acc[e], off);

    if (lane == 0) {
        int i0 = 0; float v0 = acc[0];
#pragma unroll
        for (int e = 1; e < 8; e++) if (acc[e] > v0) { v0 = acc[e]; i0 = e; }
        int i1 = -1; float v1 = -3.4e38f;
#pragma unroll
        for (int e = 0; e < 8; e++) if (e != i0 && acc[e] > v1) { v1 = acc[e]; i1 = e; }
        float r  = expf(v1 - v0);
        float g0 = 1.0f / (1.0f + r);
        float g1 = r / (1.0f + r);
        g_topk_idx[t * 2]      = i0;
        g_topk_idx[t * 2 + 1]  = i1;
        g_topk_gate[t * 2]     = g0;
        g_topk_gate[t * 2 + 1] = g1;
        atomicAdd(&g_counts[i0], 1);
        atomicAdd(&g_counts[i1], 1);
    }
}

// ---------------- stage 2: segment scan ----------------
__global__ void scan_kernel() {
    if (threadIdx.x == 0 && blockIdx.x == 0) {
        int s = 0;
        for (int e = 0; e < NEXP; e++) {
            g_seg[e] = s;
            g_cursor[e] = s;
            s += (g_counts[e] + BM - 1) & ~(BM - 1);
        }
        g_seg[NEXP] = s;
        g_seg[NEXP + 1] = s + T_TOK;
    }
}

// ---------------- stage 3: build permutation ----------------
__global__ void fill_kernel() {
    int i = blockIdx.x * blockDim.x + threadIdx.x;
    if (i < T_TOK * 2) {
        int e = g_topk_idx[i];
        int p = atomicAdd(&g_cursor[e], 1);
        g_perm_token[p] = i >> 1;
        g_inv[i] = p;
    } else if (i < T_TOK * 3) {
        int t = i - T_TOK * 2;
        g_perm_token[g_seg[NEXP] + t] = t;
    }
}

// ======================================================================
// fp16 mma.sync grouped GEMMs (KC=64, ldmatrix.x4 fragments, 3-stage cp.async)
// ======================================================================

extern __shared__ __align__(16) __half smh[];

// stage 4: SwiGLU up-projection: ACT = silu(X W1) * (X W3), fp16 out
__global__ __launch_bounds__(256, 1) void gemm1_kernel(
    const __half* __restrict__ W1T, const __half* __restrict__ W3T,
    const __half* __restrict__ SW1T, const __half* __restrict__ SW3T) {
    int base = blockIdx.y * BM;
    if (base >= g_seg[NEXP + 1]) return;
    int e = 0;
    while (g_seg[e + 1] <= base) e++;
    const __half* W1e = (e < NEXP) ? W1T + (size_t)e * HID * DM : SW1T;
    const __half* W3e = (e < NEXP) ? W3T + (size_t)e * HID * DM : SW3T;
    int nb = blockIdx.x * BN;

    int tid = threadIdx.x, lane = tid & 31, warp = tid >> 5;
    int wm = warp & 3, wn = warp >> 2;     // 4x2 warps, warp tile 32(m)x64(n)

    uint32_t sbase = smem_u32(smh);

    // producer mapping: per tile 128 rows x 8 chunks(16B); 4 rows per thread
    int ch = tid & 7;
    int rows[4];
    const __half* asrc[4];
    uint32_t dstoff[4];
#pragma unroll
    for (int i = 0; i < 4; i++) {
        int r = (tid >> 3) + 32 * i;
        rows[i] = r;
        asrc[i] = g_xh + (size_t)g_perm_token[base + r] * DM + ch * 8;
        dstoff[i] = (uint32_t)(r * ROWB + ch * 16);
    }

    // A ldmatrix offsets (x4: 16 rows x 2 k-chunks)
    uint32_t aoff[2];
#pragma unroll
    for (int mt = 0; mt < 2; mt++)
        aoff[mt] = (uint32_t)((wm * 32 + mt * 16 + (lane & 15)) * ROWB + (lane >> 4) * 16);
    // B ldmatrix.x4 offsets: pair p covers n-rows [p*16, p*16+16): m0/m1 = rows 0-7
    // k-lo/k-hi, m2/m3 = rows 8-15 k-lo/k-hi -> regs {frag nt=2p (r0,r1), frag nt=2p+1 (r2,r3)}
    uint32_t boff4[4];
#pragma unroll
    for (int p = 0; p < 4; p++)
        boff4[p] = (uint32_t)((wn * 64 + p * 16 + ((lane >> 4) & 1) * 8 + (lane & 7)) * ROWB
                              + ((lane >> 3) & 1) * 16);

    float acc1[2][8][4], acc3[2][8][4];
#pragma unroll
    for (int mt = 0; mt < 2; mt++)
#pragma unroll
        for (int nt = 0; nt < 8; nt++)
#pragma unroll
            for (int q = 0; q < 4; q++) { acc1[mt][nt][q] = 0.0f; acc3[mt][nt][q] = 0.0f; }

    const int nsl = DM / KC;   // 16

    auto issue = [&](int s) {
        uint32_t tb = sbase + (uint32_t)((s % STAGES) * 3 * SA * 2);
        int kb = s * KC;
#pragma unroll
        for (int i = 0; i < 4; i++) {
            cp16(tb + dstoff[i], asrc[i] + kb);
            cp16(tb + SA * 2 + dstoff[i], W1e + (size_t)(nb + rows[i]) * DM + kb + ch * 8);
            cp16(tb + 2 * SA * 2 + dstoff[i], W3e + (size_t)(nb + rows[i]) * DM + kb + ch * 8);
        }
        cp_commit();
    };

    issue(0);
    issue(1);

    for (int s = 0; s < nsl; s++) {
        if (s + 1 < nsl) cp_wait<1>(); else cp_wait<0>();
        __syncthreads();
        if (s + 2 < nsl) issue(s + 2);

        uint32_t tb = sbase + (uint32_t)((s % STAGES) * 3 * SA * 2);
        uint32_t aT = tb, b1T = tb + SA * 2, b3T = tb + 2 * SA * 2;
#pragma unroll
        for (int ks = 0; ks < 4; ks++) {
            uint32_t ko = ks * 32;   // 16 halves = 32 bytes
            unsigned a[2][4];
#pragma unroll
            for (int mt = 0; mt < 2; mt++) ldsm_x4(a[mt], aT + aoff[mt] + ko);
            unsigned b1[4][4], b3[4][4];
#pragma unroll
            for (int p = 0; p < 4; p++) {
                ldsm_x4(b1[p], b1T + boff4[p] + ko);
                ldsm_x4(b3[p], b3T + boff4[p] + ko);
            }
#pragma unroll
            for (int mt = 0; mt < 2; mt++)
#pragma unroll
                for (int p = 0; p < 4; p++) {
                    mma_f16(acc1[mt][2 * p],     a[mt], &b1[p][0]);
                    mma_f16(acc1[mt][2 * p + 1], a[mt], &b1[p][2]);
                    mma_f16(acc3[mt][2 * p],     a[mt], &b3[p][0]);
                    mma_f16(acc3[mt][2 * p + 1], a[mt], &b3[p][2]);
                }
        }
    }

    // epilogue: act = silu(h1) * h3, fp16
    int g = lane >> 2, tig = lane & 3;
#pragma unroll
    for (int mt = 0; mt < 2; mt++) {
#pragma unroll
        for (int nt = 0; nt < 8; nt++) {
            int r0 = base + wm * 32 + mt * 16 + g;
            int c  = nb + wn * 64 + nt * 8 + tig * 2;
            __half2 h0 = __floats2half2_rn(silu_f(acc1[mt][nt][0]) * acc3[mt][nt][0],
                                           silu_f(acc1[mt][nt][1]) * acc3[mt][nt][1]);
            __half2 h1 = __floats2half2_rn(silu_f(acc1[mt][nt][2]) * acc3[mt][nt][2],
                                           silu_f(acc1[mt][nt][3]) * acc3[mt][nt][3]);
            *reinterpret_cast<__half2*>(g_acth + (size_t)r0 * HID + c)       = h0;
            *reinterpret_cast<__half2*>(g_acth + (size_t)(r0 + 8) * HID + c) = h1;
        }
    }
}

// stage 5: down-projection: Y = ACT @ W2, fp32 out
__global__ __launch_bounds__(256, 1) void gemm2_kernel(
    const __half* __restrict__ W2T, const __half* __restrict__ SW2T) {
    int base = blockIdx.y * BM;
    if (base >= g_seg[NEXP + 1]) return;
    int e = 0;
    while (g_seg[e + 1] <= base) e++;
    const __half* W2e = (e < NEXP) ? W2T + (size_t)e * DM * HID : SW2T;
    int nb = blockIdx.x * BN;

    int tid = threadIdx.x, lane = tid & 31, warp = tid >> 5;
    int wm = warp & 3, wn = warp >> 2;

    uint32_t sbase = smem_u32(smh);

    int ch = tid & 7;
    int rows[4];
    uint32_t dstoff[4];
#pragma unroll
    for (int i = 0; i < 4; i++) {
        int r = (tid >> 3) + 32 * i;
        rows[i] = r;
        dstoff[i] = (uint32_t)(r * ROWB + ch * 16);
    }

    uint32_t aoff[2];
#pragma unroll
    for (int mt = 0; mt < 2; mt++)
        aoff[mt] = (uint32_t)((wm * 32 + mt * 16 + (lane & 15)) * ROWB + (lane >> 4) * 16);
    uint32_t boff4[4];
#pragma unroll
    for (int p = 0; p < 4; p++)
        boff4[p] = (uint32_t)((wn * 64 + p * 16 + ((lane >> 4) & 1) * 8 + (lane & 7)) * ROWB
                              + ((lane >> 3) & 1) * 16);

    float acc[2][8][4];
#pragma unroll
    for (int mt = 0; mt < 2; mt++)
#pragma unroll
        for (int nt = 0; nt < 8; nt++)
#pragma unroll
            for (int q = 0; q < 4; q++) acc[mt][nt][q] = 0.0f;

    const int nsl = HID / KC;   // 32

    auto issue = [&](int s) {
        uint32_t tb = sbase + (uint32_t)((s % STAGES) * 2 * SA * 2);
        int kb = s * KC;
#pragma unroll
        for (int i = 0; i < 4; i++) {
            cp16(tb + dstoff[i], g_acth + (size_t)(base + rows[i]) * HID + kb + ch * 8);
            cp16(tb + SA * 2 + dstoff[i], W2e + (size_t)(nb + rows[i]) * HID + kb + ch * 8);
        }
        cp_commit();
    };

    issue(0);
    issue(1);

    for (int s = 0; s < nsl; s++) {
        if (s + 1 < nsl) cp_wait<1>(); else cp_wait<0>();
        __syncthreads();
        if (s + 2 < nsl) issue(s + 2);

        uint32_t tb = sbase + (uint32_t)((s % STAGES) * 2 * SA * 2);
        uint32_t aT = tb, bT = tb + SA * 2;
#pragma unroll
        for (int ks = 0; ks < 4; ks++) {
            uint32_t ko = ks * 32;
            unsigned a[2][4];
#pragma unroll
            for (int mt = 0; mt < 2; mt++) ldsm_x4(a[mt], aT + aoff[mt] + ko);
            unsigned b[4][4];
#pragma unroll
            for (int p = 0; p < 4; p++) ldsm_x4(b[p], bT + boff4[p] + ko);
#pragma unroll
            for (int mt = 0; mt < 2; mt++)
#pragma unroll
                for (int p = 0; p < 4; p++) {
                    mma_f16(acc[mt][2 * p],     a[mt], &b[p][0]);
                    mma_f16(acc[mt][2 * p + 1], a[mt], &b[p][2]);
                }
        }
    }

    int g = lane >> 2, tig = lane & 3;
#pragma unroll
    for (int mt = 0; mt < 2; mt++) {
#pragma unroll
        for (int nt = 0; nt < 8; nt++) {
            int r0 = base + wm * 32 + mt * 16 + g;
            int c  = nb + wn * 64 + nt * 8 + tig * 2;
            float2 o0, o1;
            o0.x = acc[mt][nt][0]; o0.y = acc[mt][nt][1];
            o1.x = acc[mt][nt][2]; o1.y = acc[mt][nt][3];
            *reinterpret_cast<float2*>(g_y + (size_t)r0 * DM + c)       = o0;
            *reinterpret_cast<float2*>(g_y + (size_t)(r0 + 8) * DM + c) = o1;
        }
    }
}

// ---------------- stage 6: combine shared + gated routed (float4) ----------------
__global__ void combine_kernel(float* __restrict__ OUT) {
    int i = blockIdx.x * blockDim.x + threadIdx.x;   // over float4s
    if (i >= T_TOK * DM / 4) return;
    int t  = i >> 8;            // DM/4 = 256 float4 per token
    int d4 = i & 255;
    int s8 = g_seg[NEXP];
    int p0 = g_inv[t * 2];
    int p1 = g_inv[t * 2 + 1];
    float g0 = g_topk_gate[t * 2];
    float g1 = g_topk_gate[t * 2 + 1];
    float4 vs = *reinterpret_cast<const float4*>(g_y + (size_t)(s8 + t) * DM + d4 * 4);
    float4 v0 = *reinterpret_cast<const float4*>(g_y + (size_t)p0 * DM + d4 * 4);
    float4 v1 = *reinterpret_cast<const float4*>(g_y + (size_t)p1 * DM + d4 * 4);
    float4 o;
    o.x = vs.x + g0 * v0.x + g1 * v1.x;
    o.y = vs.y + g0 * v0.y + g1 * v1.y;
    o.z = vs.z + g0 * v0.z + g1 * v1.z;
    o.w = vs.w + g0 * v0.w + g1 * v1.w;
    reinterpret_cast<float4*>(OUT)[i] = o;
}

// ---------------- launch ----------------
#define G1_SMEM (STAGES * 3 * SA * 2)   // 165888 bytes
#define G2_SMEM (STAGES * 2 * SA * 2)   // 110592 bytes

extern "C" void kernel_launch(void* const* d_in, const int* in_sizes, int n_in,
                              void* d_out, int out_size) {
    (void)in_sizes; (void)n_in; (void)out_size;
    const float* x   = (const float*)d_in[0];
    const float* wr  = (const float*)d_in[1];
    const float* w1  = (const float*)d_in[2];
    const float* w3  = (const float*)d_in[3];
    const float* w2  = (const float*)d_in[4];
    const float* sw1 = (const float*)d_in[5];
    const float* sw3 = (const float*)d_in[6];
    const float* sw2 = (const float*)d_in[7];
    float* out = (float*)d_out;

    __half *w1t, *w3t, *w2t, *sw1t, *sw3t, *sw2t;
    cudaGetSymbolAddress((void**)&w1t,  g_w1t);
    cudaGetSymbolAddress((void**)&w3t,  g_w3t);
    cudaGetSymbolAddress((void**)&w2t,  g_w2t);
    cudaGetSymbolAddress((void**)&sw1t, g_sw1t);
    cudaGetSymbolAddress((void**)&sw3t, g_sw3t);
    cudaGetSymbolAddress((void**)&sw2t, g_sw2t);

    cudaFuncSetAttribute(gemm1_kernel, cudaFuncAttributeMaxDynamicSharedMemorySize, G1_SMEM);
    cudaFuncSetAttribute(gemm2_kernel, cudaFuncAttributeMaxDynamicSharedMemorySize, G2_SMEM);

    reset_kernel<<<52, 256>>>();
    router_kernel<<<512, 256>>>(x, wr);
    scan_kernel<<<1, 32>>>();
    fill_kernel<<<48, 256>>>();

    cvt_x_kernel<<<(T_TOK * DM / 4) / 256, 256>>>(x);
    transpose_cvt_kernel<<<dim3(HID / 64, DM / 64, NEXP), 256>>>(w1, w1t, DM, HID);
    transpose_cvt_kernel<<<dim3(HID / 64, DM / 64, NEXP), 256>>>(w3, w3t, DM, HID);
    transpose_cvt_kernel<<<dim3(DM / 64, HID / 64, NEXP), 256>>>(w2, w2t, HID, DM);
    transpose_cvt_kernel<<<dim3(HID / 64, DM / 64, 1), 256>>>(sw1, sw1t, DM, HID);
    transpose_cvt_kernel<<<dim3(HID / 64, DM / 64, 1), 256>>>(sw3, sw3t, DM, HID);
    transpose_cvt_kernel<<<dim3(DM / 64, HID / 64, 1), 256>>>(sw2, sw2t, HID, DM);

    gemm1_kernel<<<dim3(HID / BN, MAXROWS / BM), 256, G1_SMEM>>>(w1t, w3t, sw1t, sw3t);
    gemm2_kernel<<<dim3(DM / BN, MAXROWS / BM), 256, G2_SMEM>>>(w2t, sw2t);

    combine_kernel<<<(T_TOK * DM / 4 + 255) / 256, 256>>>(out);
}